// round 14
// baseline (speedup 1.0000x reference)
#include <cuda_runtime.h>
#include <cuda_fp16.h>
#include <math.h>
#include <stdint.h>

// ---------------- problem constants ----------------
#define NN      50000      // nodes
#define EMAX    800000     // edges (before self loops)
#define ETOT    (EMAX + NN)
#define FEAT    256        // NFEAT = NHEADS*NHID = NOUT = 256
#define NHEADS  4
#define NHID    64
#define NEG_SLOPE 0.2f
#define BN_EPS  1e-5f
#define LN_EPS  1e-5f

// ---------------- scratch (device globals; no runtime alloc) ----------------
// Buffer lifecycle (per call):
//   g_xh : [transp_conv] x->fp16 --(gemm1 reads)--> dead --> [gemm2 writes xp2] --> agg2 gathers
//   g_xph: [gemm1 writes xp1] --> agg1 gathers
//   g_h1h: [agg1 writes] --> gemm2 reads
__device__ __half g_xh[NN * FEAT];
__device__ __half g_xph[NN * FEAT];
__device__ __half g_h1h[NN * FEAT];
__device__ __half g_wth1[FEAT * FEAT];         // W1^T, fp16, [n][k]
__device__ __half g_wth2[FEAT * FEAT];         // W2^T, fp16, [n][k]
__device__ float g_asrc[NN * NHEADS];          // layer-1 logits (per head)
__device__ float g_adst[NN * NHEADS];
__device__ float g_asrc2[NN];                  // layer-2 logits (atomic-accumulated)
__device__ float g_adst2[NN];
__device__ int   g_count[NN];                  // zero at rest (restored by fill_kernel)
__device__ int   g_rowptr[NN + 1];
__device__ int   g_cursor[NN];
__device__ int   g_csrsrc[ETOT];

// ---------------- weight transpose + x->fp16 convert (fast; gates gemm1) ----------------
// blocks [0,128): transpose W1/W2 to fp16. blocks [128, 128+nblk_x): convert x.
__global__ void transp_conv_kernel(const float* __restrict__ W1,
                                   const float* __restrict__ W2,
                                   const float* __restrict__ x, int nx8) {
    int tb = blockIdx.x;
    if (tb < 128) {
        __shared__ float tile[32][33];
        int z = tb >> 6;                        // 0 = W1, 1 = W2
        int rem = tb & 63;
        int bx = (rem & 7) * 32, by = (rem >> 3) * 32;
        const float* W  = (z == 0) ? W1 : W2;
        __half* Wt = (z == 0) ? g_wth1 : g_wth2;
        int tx = threadIdx.x & 31, ty = threadIdx.x >> 5;   // 32 x 8
        #pragma unroll
        for (int i = 0; i < 32; i += 8)
            tile[ty + i][tx] = W[(by + ty + i) * FEAT + bx + tx];
        __syncthreads();
        #pragma unroll
        for (int i = 0; i < 32; i += 8)
            Wt[(bx + ty + i) * FEAT + by + tx] = __float2half_rn(tile[tx][ty + i]);
        return;
    }
    int i8 = (tb - 128) * blockDim.x + threadIdx.x;
    if (i8 < nx8) {
        const float4* src = reinterpret_cast<const float4*>(x + (size_t)i8 * 8);
        float4 a = src[0], b = src[1];
        __half2 h0 = __float22half2_rn(make_float2(a.x, a.y));
        __half2 h1 = __float22half2_rn(make_float2(a.z, a.w));
        __half2 h2 = __float22half2_rn(make_float2(b.x, b.y));
        __half2 h3 = __float22half2_rn(make_float2(b.z, b.w));
        uint4 o;
        o.x = *reinterpret_cast<uint32_t*>(&h0);
        o.y = *reinterpret_cast<uint32_t*>(&h1);
        o.z = *reinterpret_cast<uint32_t*>(&h2);
        o.w = *reinterpret_cast<uint32_t*>(&h3);
        *reinterpret_cast<uint4*>(g_xh + (size_t)i8 * 8) = o;
    }
}

// ---------------- edge histogram (runs concurrent with gemm1) ----------------
__global__ void count_kernel(const int* __restrict__ ei, int E) {
    int i = blockIdx.x * blockDim.x + threadIdx.x;
    if (i < E) {
        int d = ei[E + i];      // dst row of edge_index
        atomicAdd(&g_count[d], 1);
    }
}

// single-block scan, 1024 threads, 4 elements/thread; adds +1 per node (self loop)
__global__ void scan_kernel(int n) {
    __shared__ int warpsum[32];
    __shared__ int s_carry;
    int tid = threadIdx.x, lane = tid & 31, wid = tid >> 5;
    if (tid == 0) { s_carry = 0; g_rowptr[0] = 0; }
    __syncthreads();
    for (int base = 0; base < n; base += 4096) {
        int i = base + tid * 4;
        int v0 = 0, v1 = 0, v2 = 0, v3 = 0;
        if (i + 3 < n) {
            int4 q = *reinterpret_cast<const int4*>(&g_count[i]);
            v0 = q.x + 1; v1 = q.y + 1; v2 = q.z + 1; v3 = q.w + 1;  // +1 self loop
        } else {
            if (i     < n) v0 = g_count[i]     + 1;
            if (i + 1 < n) v1 = g_count[i + 1] + 1;
            if (i + 2 < n) v2 = g_count[i + 2] + 1;
        }
        int t = v0 + v1 + v2 + v3;
        int x = t;
        #pragma unroll
        for (int off = 1; off < 32; off <<= 1) {
            int y = __shfl_up_sync(0xffffffffu, x, off);
            if (lane >= off) x += y;
        }
        if (lane == 31) warpsum[wid] = x;
        __syncthreads();
        int woff = 0, tot = 0;
        #pragma unroll
        for (int w = 0; w < 32; w++) {
            int ws = warpsum[w];
            if (w < wid) woff += ws;
            tot += ws;
        }
        int carry = s_carry;
        int excl = carry + woff + x - t;   // exclusive prefix at element i
        int e1 = excl + v0, e2 = e1 + v1, e3 = e2 + v2;
        if (i     < n) { g_cursor[i]     = excl; g_rowptr[i + 1] = e1; }
        if (i + 1 < n) { g_cursor[i + 1] = e1;   g_rowptr[i + 2] = e2; }
        if (i + 2 < n) { g_cursor[i + 2] = e2;   g_rowptr[i + 3] = e3; }
        if (i + 3 < n) { g_cursor[i + 3] = e3;   g_rowptr[i + 4] = e3 + v3; }
        __syncthreads();
        if (tid == 0) s_carry = carry + tot;
        __syncthreads();
    }
}

// fill also: re-zeros g_count (restores rest state) and zeros asrc2/adst2.
__global__ void fill_kernel(const int* __restrict__ ei, int E, int n) {
    int i = blockIdx.x * blockDim.x + threadIdx.x;
    int tot = E + n;
    if (i >= tot) return;
    int s, d;
    if (i < E) {
        s = ei[i]; d = ei[E + i];
        if (i < n) g_count[i] = 0;
    } else {
        s = d = i - E;
        g_asrc2[d] = 0.f;
        g_adst2[d] = 0.f;
    }
    int pos = atomicAdd(&g_cursor[d], 1);
    g_csrsrc[pos] = s;
}

// ---------------- FP16 tensor-core GEMM (m16n8k16), fp16 A/B/out, fp32 accum ----------------
#define PH 40                 // smem pitch in halfs (80B = 5x16B, ldmatrix conflict-free)
#define STAGE_BYTES (2 * 128 * PH * 2)   // As + Bs per stage

__device__ __forceinline__ void ldsm_x4(uint32_t addr, uint32_t& r0, uint32_t& r1,
                                        uint32_t& r2, uint32_t& r3) {
    asm volatile("ldmatrix.sync.aligned.m8n8.x4.shared.b16 {%0,%1,%2,%3}, [%4];"
                 : "=r"(r0), "=r"(r1), "=r"(r2), "=r"(r3) : "r"(addr));
}

__device__ __forceinline__ void mma_fp16(float* c, const uint32_t* a, const uint32_t* b) {
    asm volatile(
        "mma.sync.aligned.m16n8k16.row.col.f32.f16.f16.f32 "
        "{%0,%1,%2,%3}, {%4,%5,%6,%7}, {%8,%9}, {%0,%1,%2,%3};"
        : "+f"(c[0]), "+f"(c[1]), "+f"(c[2]), "+f"(c[3])
        : "r"(a[0]), "r"(a[1]), "r"(a[2]), "r"(a[3]), "r"(b[0]), "r"(b[1]));
}

__device__ __forceinline__ void cp16(uint32_t saddr, const void* gptr, uint32_t srcsize) {
    asm volatile("cp.async.ca.shared.global [%0], [%1], 16, %2;\n"
                 :: "r"(saddr), "l"(gptr), "r"(srcsize));
}

template<int HEADS>
__global__ __launch_bounds__(256) void gemm_att_kernel(
    const __half* __restrict__ A, const __half* __restrict__ Wt,
    __half* __restrict__ Ch,
    const float* __restrict__ attS, const float* __restrict__ attD,
    float* __restrict__ oS, float* __restrict__ oD, int M)
{
    __shared__ __half smem[2 * 2 * 128 * PH];
    const int K = 256;
    int tid = threadIdx.x;
    int lane = tid & 31;
    int warp = tid >> 5;
    int wm = warp >> 1;          // 0..3
    int wn = warp & 1;           // 0..1
    int block_row = blockIdx.x * 128;
    int block_col = blockIdx.y * 128;

    uint32_t s_base = (uint32_t)__cvta_generic_to_shared(smem);
    uint32_t sA = s_base;
    uint32_t sB = s_base + 128 * PH * 2;

    int c0i = tid * 2, c1i = tid * 2 + 1;
    int ar0 = c0i >> 2, ac0 = (c0i & 3) * 8;   // col offset in halfs
    int ar1 = c1i >> 2, ac1 = (c1i & 3) * 8;
    uint32_t dstA0 = sA + (uint32_t)(ar0 * PH + ac0) * 2;
    uint32_t dstA1 = sA + (uint32_t)(ar1 * PH + ac1) * 2;
    uint32_t dstB0 = sB + (uint32_t)(ar0 * PH + ac0) * 2;
    uint32_t dstB1 = sB + (uint32_t)(ar1 * PH + ac1) * 2;
    int grA0 = block_row + ar0, grA1 = block_row + ar1;
    uint32_t szA0 = (grA0 < M) ? 16u : 0u;
    uint32_t szA1 = (grA1 < M) ? 16u : 0u;
    if (grA0 >= M) grA0 = 0;
    if (grA1 >= M) grA1 = 0;
    const __half* srcA0 = A + (size_t)grA0 * K + ac0;
    const __half* srcA1 = A + (size_t)grA1 * K + ac1;
    const __half* srcB0 = Wt + (size_t)(block_col + ar0) * K + ac0;
    const __half* srcB1 = Wt + (size_t)(block_col + ar1) * K + ac1;

    int g = lane >> 3, r = lane & 7;
    int a_row_l = (g & 1) * 8 + r;
    int a_koff  = (g >> 1) * 8;                // halfs
    uint32_t a_base[2];
    #pragma unroll
    for (int mt = 0; mt < 2; mt++)
        a_base[mt] = sA + (uint32_t)((wm * 32 + mt * 16 + a_row_l) * PH + a_koff) * 2;
    int b_row_l = (g >> 1) * 8 + r;
    int b_koff  = (g & 1) * 8;                 // halfs
    uint32_t b_base[4];
    #pragma unroll
    for (int np = 0; np < 4; np++)
        b_base[np] = sB + (uint32_t)((wn * 64 + np * 16 + b_row_l) * PH + b_koff) * 2;

    float acc[2][8][4];
    #pragma unroll
    for (int mt = 0; mt < 2; mt++)
        #pragma unroll
        for (int nt = 0; nt < 8; nt++)
            #pragma unroll
            for (int q = 0; q < 4; q++) acc[mt][nt][q] = 0.f;

    cp16(dstA0, srcA0, szA0);
    cp16(dstA1, srcA1, szA1);
    cp16(dstB0, srcB0, 16u);
    cp16(dstB1, srcB1, 16u);
    asm volatile("cp.async.commit_group;\n" ::);

    const int NITER = K / 32;   // 8
    for (int it = 0; it < NITER; it++) {
        int buf = it & 1;
        if (it + 1 < NITER) {
            uint32_t off = ((it + 1) & 1) * STAGE_BYTES;
            int k0 = (it + 1) * 32;
            cp16(dstA0 + off, srcA0 + k0, szA0);
            cp16(dstA1 + off, srcA1 + k0, szA1);
            cp16(dstB0 + off, srcB0 + k0, 16u);
            cp16(dstB1 + off, srcB1 + k0, 16u);
            asm volatile("cp.async.commit_group;\n" ::);
            asm volatile("cp.async.wait_group 1;\n" ::);
        } else {
            asm volatile("cp.async.wait_group 0;\n" ::);
        }
        __syncthreads();

        uint32_t soff = buf * STAGE_BYTES;
        #pragma unroll
        for (int ks = 0; ks < 32; ks += 16) {   // two k16 steps per stage
            uint32_t a[2][4], b[4][4];
            #pragma unroll
            for (int mt = 0; mt < 2; mt++)
                ldsm_x4(a_base[mt] + soff + ks * 2, a[mt][0], a[mt][1], a[mt][2], a[mt][3]);
            #pragma unroll
            for (int np = 0; np < 4; np++)
                ldsm_x4(b_base[np] + soff + ks * 2, b[np][0], b[np][1], b[np][2], b[np][3]);
            #pragma unroll
            for (int mt = 0; mt < 2; mt++)
                #pragma unroll
                for (int nt = 0; nt < 8; nt++)
                    mma_fp16(acc[mt][nt], a[mt], &b[nt >> 1][(nt & 1) * 2]);
        }
        __syncthreads();
    }

    // ---- epilogue: fp16 stores ----
    int cr = lane >> 2;
    int cc = (lane & 3) * 2;
    #pragma unroll
    for (int mt = 0; mt < 2; mt++) {
        int row0 = block_row + wm * 32 + mt * 16 + cr;
        #pragma unroll
        for (int nt = 0; nt < 8; nt++) {
            int col = block_col + wn * 64 + nt * 8 + cc;
            if (row0 < M)
                *reinterpret_cast<__half2*>(Ch + (size_t)row0 * 256 + col) =
                    __float22half2_rn(make_float2(acc[mt][nt][0], acc[mt][nt][1]));
            if (row0 + 8 < M)
                *reinterpret_cast<__half2*>(Ch + (size_t)(row0 + 8) * 256 + col) =
                    __float22half2_rn(make_float2(acc[mt][nt][2], acc[mt][nt][3]));
        }
    }

    // ---- epilogue: fused attention-logit partial dots over this warp's 64 cols ----
    float ps[2][2] = {{0.f,0.f},{0.f,0.f}};
    float pd[2][2] = {{0.f,0.f},{0.f,0.f}};
    #pragma unroll
    for (int mt = 0; mt < 2; mt++) {
        #pragma unroll
        for (int nt = 0; nt < 8; nt++) {
            int lc = nt * 8 + cc;
            int idx = (HEADS == 4) ? ((blockIdx.y * 2 + wn) * 64 + lc)
                                   : (block_col + wn * 64 + lc);
            float as0 = attS[idx], as1 = attS[idx + 1];
            float ad0 = attD[idx], ad1 = attD[idx + 1];
            ps[mt][0] += acc[mt][nt][0] * as0 + acc[mt][nt][1] * as1;
            ps[mt][1] += acc[mt][nt][2] * as0 + acc[mt][nt][3] * as1;
            pd[mt][0] += acc[mt][nt][0] * ad0 + acc[mt][nt][1] * ad1;
            pd[mt][1] += acc[mt][nt][2] * ad0 + acc[mt][nt][3] * ad1;
        }
    }
    #pragma unroll
    for (int mt = 0; mt < 2; mt++)
        #pragma unroll
        for (int hf = 0; hf < 2; hf++) {
            ps[mt][hf] += __shfl_xor_sync(0xffffffffu, ps[mt][hf], 1);
            ps[mt][hf] += __shfl_xor_sync(0xffffffffu, ps[mt][hf], 2);
            pd[mt][hf] += __shfl_xor_sync(0xffffffffu, pd[mt][hf], 1);
            pd[mt][hf] += __shfl_xor_sync(0xffffffffu, pd[mt][hf], 2);
        }
    if ((lane & 3) == 0) {
        #pragma unroll
        for (int mt = 0; mt < 2; mt++)
            #pragma unroll
            for (int hf = 0; hf < 2; hf++) {
                int node = block_row + wm * 32 + mt * 16 + cr + hf * 8;
                if (node < M) {
                    if (HEADS == 4) {
                        int head = blockIdx.y * 2 + wn;
                        oS[node * 4 + head] = ps[mt][hf];
                        oD[node * 4 + head] = pd[mt][hf];
                    } else {
                        atomicAdd(&oS[node], ps[mt][hf]);
                        atomicAdd(&oD[node], pd[mt][hf]);
                    }
                }
            }
    }
}

__device__ __forceinline__ float leaky(float x) {
    return (x > 0.f) ? x : NEG_SLOPE * x;
}

__device__ __forceinline__ void unpack8h(uint4 u, float* f) {
    float2 a = __half22float2(*reinterpret_cast<__half2*>(&u.x));
    float2 b = __half22float2(*reinterpret_cast<__half2*>(&u.y));
    float2 c = __half22float2(*reinterpret_cast<__half2*>(&u.z));
    float2 d = __half22float2(*reinterpret_cast<__half2*>(&u.w));
    f[0] = a.x; f[1] = a.y; f[2] = b.x; f[3] = b.y;
    f[4] = c.x; f[5] = c.y; f[6] = d.x; f[7] = d.y;
}

__device__ __forceinline__ uint4 pack8h(const float* f) {
    __half2 h0 = __float22half2_rn(make_float2(f[0], f[1]));
    __half2 h1 = __float22half2_rn(make_float2(f[2], f[3]));
    __half2 h2 = __float22half2_rn(make_float2(f[4], f[5]));
    __half2 h3 = __float22half2_rn(make_float2(f[6], f[7]));
    uint4 o;
    o.x = *reinterpret_cast<uint32_t*>(&h0);
    o.y = *reinterpret_cast<uint32_t*>(&h1);
    o.z = *reinterpret_cast<uint32_t*>(&h2);
    o.w = *reinterpret_cast<uint32_t*>(&h3);
    return o;
}

// ---------------- aggregation, layer 1 (4 heads, fp16 gather) + bias + ELU -> fp16 h1 ----------------
__global__ __launch_bounds__(64) void agg1_kernel(const __half* __restrict__ xph,
                            const float* __restrict__ bias,
                            __half* __restrict__ out, int n)
{
    int node = (blockIdx.x * blockDim.x + threadIdx.x) >> 5;
    if (node >= n) return;
    int lane = threadIdx.x & 31;
    int h  = lane >> 3;         // 8 lanes per head
    int c0 = lane * 8;
    float ad = g_adst[node * NHEADS + h];
    int beg = g_rowptr[node], end = g_rowptr[node + 1];
    float m = -1e30f, s = 0.f;
    float acc[8] = {0,0,0,0,0,0,0,0};
    int p = beg;
    for (; p + 1 < end; p += 2) {
        int j0 = g_csrsrc[p];
        int j1 = g_csrsrc[p + 1];
        float e0 = leaky(g_asrc[j0 * NHEADS + h] + ad);
        float e1 = leaky(g_asrc[j1 * NHEADS + h] + ad);
        uint4 u0 = *reinterpret_cast<const uint4*>(xph + (size_t)j0 * FEAT + c0);
        uint4 u1 = *reinterpret_cast<const uint4*>(xph + (size_t)j1 * FEAT + c0);
        float fa[8], fb[8];
        unpack8h(u0, fa);
        unpack8h(u1, fb);
        float mn = fmaxf(m, fmaxf(e0, e1));
        float corr = __expf(m - mn);
        float p0   = __expf(e0 - mn);
        float p1   = __expf(e1 - mn);
        s = s * corr + p0 + p1;
        #pragma unroll
        for (int k = 0; k < 8; k++)
            acc[k] = acc[k] * corr + p0 * fa[k] + p1 * fb[k];
        m = mn;
    }
    if (p < end) {
        int j = g_csrsrc[p];
        float e = leaky(g_asrc[j * NHEADS + h] + ad);
        uint4 u = *reinterpret_cast<const uint4*>(xph + (size_t)j * FEAT + c0);
        float fa[8];
        unpack8h(u, fa);
        float mn = fmaxf(m, e);
        float corr = __expf(m - mn);
        float pw   = __expf(e - mn);
        s = s * corr + pw;
        #pragma unroll
        for (int k = 0; k < 8; k++)
            acc[k] = acc[k] * corr + pw * fa[k];
    }
    float inv = 1.f / s;
    const float4* b4 = reinterpret_cast<const float4*>(bias + c0);
    float4 bb0 = b4[0], bb1 = b4[1];
    float vb[8] = {bb0.x, bb0.y, bb0.z, bb0.w, bb1.x, bb1.y, bb1.z, bb1.w};
    float v[8];
    #pragma unroll
    for (int k = 0; k < 8; k++) {
        float t = acc[k] * inv + vb[k];
        v[k] = (t > 0.f) ? t : expm1f(t);   // ELU
    }
    *reinterpret_cast<uint4*>(out + (size_t)node * FEAT + c0) = pack8h(v);
}

// ---------------- aggregation, layer 2 (1 head, fp16 gather) + bias + ELU + BN + LN ----------------
__global__ __launch_bounds__(64) void agg2_kernel(const __half* __restrict__ xp2,
                            const float* __restrict__ bias,
                            const float* __restrict__ bn_gamma,
                            const float* __restrict__ bn_beta,
                            const float* __restrict__ bn_mean,
                            const float* __restrict__ bn_var,
                            const float* __restrict__ ln_gamma,
                            const float* __restrict__ ln_beta,
                            float* __restrict__ out, int n)
{
    int node = (blockIdx.x * blockDim.x + threadIdx.x) >> 5;
    if (node >= n) return;
    int lane = threadIdx.x & 31;
    int c0 = lane * 8;
    float ad = g_adst2[node];
    int beg = g_rowptr[node], end = g_rowptr[node + 1];
    float m = -1e30f, s = 0.f;
    float acc[8] = {0,0,0,0,0,0,0,0};
    int p = beg;
    for (; p + 1 < end; p += 2) {
        int j0 = g_csrsrc[p];
        int j1 = g_csrsrc[p + 1];
        float e0 = leaky(g_asrc2[j0] + ad);
        float e1 = leaky(g_asrc2[j1] + ad);
        uint4 u0 = *reinterpret_cast<const uint4*>(xp2 + (size_t)j0 * FEAT + c0);
        uint4 u1 = *reinterpret_cast<const uint4*>(xp2 + (size_t)j1 * FEAT + c0);
        float fa[8], fb[8];
        unpack8h(u0, fa);
        unpack8h(u1, fb);
        float mn = fmaxf(m, fmaxf(e0, e1));
        float corr = __expf(m - mn);
        float p0   = __expf(e0 - mn);
        float p1   = __expf(e1 - mn);
        s = s * corr + p0 + p1;
        #pragma unroll
        for (int k = 0; k < 8; k++)
            acc[k] = acc[k] * corr + p0 * fa[k] + p1 * fb[k];
        m = mn;
    }
    if (p < end) {
        int j = g_csrsrc[p];
        float e = leaky(g_asrc2[j] + ad);
        uint4 u = *reinterpret_cast<const uint4*>(xp2 + (size_t)j * FEAT + c0);
        float fa[8];
        unpack8h(u, fa);
        float mn = fmaxf(m, e);
        float corr = __expf(m - mn);
        float pw   = __expf(e - mn);
        s = s * corr + pw;
        #pragma unroll
        for (int k = 0; k < 8; k++)
            acc[k] = acc[k] * corr + pw * fa[k];
    }
    float inv = 1.f / s;
    float v[8];
    #pragma unroll
    for (int k = 0; k < 8; k++) {
        int c = c0 + k;
        float x = acc[k] * inv + bias[c];
        x = (x > 0.f) ? x : expm1f(x);                           // ELU
        x = (x - bn_mean[c]) * rsqrtf(bn_var[c] + BN_EPS) * bn_gamma[c] + bn_beta[c];  // BN eval
        v[k] = x;
    }
    // LayerNorm over 256 channels (warp = row, 8 ch/lane)
    float lsum = 0.f;
    #pragma unroll
    for (int k = 0; k < 8; k++) lsum += v[k];
    #pragma unroll
    for (int off = 16; off; off >>= 1) lsum += __shfl_xor_sync(0xffffffffu, lsum, off);
    float mu = lsum * (1.f / 256.f);
    float lvar = 0.f;
    #pragma unroll
    for (int k = 0; k < 8; k++) { float d = v[k] - mu; lvar += d * d; }
    #pragma unroll
    for (int off = 16; off; off >>= 1) lvar += __shfl_xor_sync(0xffffffffu, lvar, off);
    float r = rsqrtf(lvar * (1.f / 256.f) + LN_EPS);
    float w[8];
    #pragma unroll
    for (int k = 0; k < 8; k++) {
        int c = c0 + k;
        w[k] = (v[k] - mu) * r * ln_gamma[c] + ln_beta[c];
    }
    float4 o0 = make_float4(w[0], w[1], w[2], w[3]);
    float4 o1 = make_float4(w[4], w[5], w[6], w[7]);
    float4* orow = reinterpret_cast<float4*>(out + (size_t)node * FEAT + c0);
    orow[0] = o0; orow[1] = o1;
}

// ---------------- launch ----------------
extern "C" void kernel_launch(void* const* d_in, const int* in_sizes, int n_in,
                              void* d_out, int out_size)
{
    const float* x        = (const float*)d_in[0];
    const int*   ei       = (const int*)  d_in[1];
    const float* W1       = (const float*)d_in[2];
    const float* att_src1 = (const float*)d_in[3];
    const float* att_dst1 = (const float*)d_in[4];
    const float* bias1    = (const float*)d_in[5];
    const float* W2       = (const float*)d_in[6];
    const float* att_src2 = (const float*)d_in[7];
    const float* att_dst2 = (const float*)d_in[8];
    const float* bias2    = (const float*)d_in[9];
    const float* bn_gamma = (const float*)d_in[10];
    const float* bn_beta  = (const float*)d_in[11];
    const float* bn_mean  = (const float*)d_in[12];
    const float* bn_var   = (const float*)d_in[13];
    const float* ln_gamma = (const float*)d_in[14];
    const float* ln_beta  = (const float*)d_in[15];
    float* out = (float*)d_out;

    int n = in_sizes[0] / FEAT;      // 50000
    int E = in_sizes[1] / 2;         // 800000
    if (n > NN) n = NN;
    if (E > EMAX) E = EMAX;

    float *asrc, *adst, *asrc2, *adst2;
    __half *xh, *xph, *h1h, *wth1, *wth2;
    cudaGetSymbolAddress((void**)&xh,    g_xh);
    cudaGetSymbolAddress((void**)&xph,   g_xph);
    cudaGetSymbolAddress((void**)&h1h,   g_h1h);
    cudaGetSymbolAddress((void**)&wth1,  g_wth1);
    cudaGetSymbolAddress((void**)&wth2,  g_wth2);
    cudaGetSymbolAddress((void**)&asrc,  g_asrc);
    cudaGetSymbolAddress((void**)&adst,  g_adst);
    cudaGetSymbolAddress((void**)&asrc2, g_asrc2);
    cudaGetSymbolAddress((void**)&adst2, g_adst2);

    // lazy side-stream / event creation (first call is outside graph capture)
    static cudaStream_t s_side = nullptr;
    static cudaEvent_t  s_evF = nullptr, s_evW = nullptr, s_evJ = nullptr;
    if (s_side == nullptr) {
        cudaStreamCreateWithFlags(&s_side, cudaStreamNonBlocking);
        cudaEventCreateWithFlags(&s_evF, cudaEventDisableTiming);
        cudaEventCreateWithFlags(&s_evW, cudaEventDisableTiming);
        cudaEventCreateWithFlags(&s_evJ, cudaEventDisableTiming);
    }

    // --- fork ---
    cudaEventRecord(s_evF, 0);
    cudaStreamWaitEvent(s_side, s_evF, 0);

    // side: fast prep first (gates gemm1), then CSR chain (overlaps gemm1)
    int nx8 = n * FEAT / 8;
    int nblk_x = (nx8 + 255) / 256;
    transp_conv_kernel<<<128 + nblk_x, 256, 0, s_side>>>(W1, W2, x, nx8);   // launch 1
    cudaEventRecord(s_evW, s_side);
    count_kernel<<<(E + 255) / 256, 256, 0, s_side>>>(ei, E);               // launch 2
    scan_kernel<<<1, 1024, 0, s_side>>>(n);                                 // launch 3

    // main: layer-1 GEMM (waits only on transp_conv; overlaps count/scan/fill)
    cudaStreamWaitEvent(0, s_evW, 0);
    dim3 ggrid((n + 127) / 128, FEAT / 128);
    gemm_att_kernel<4><<<ggrid, 256>>>(xh, wth1, xph,                       // launch 4 (profiled)
                                       att_src1, att_dst1, asrc, adst, n);

    // side: fill completes the CSR
    fill_kernel<<<(E + n + 255) / 256, 256, 0, s_side>>>(ei, E, n);         // launch 5
    cudaEventRecord(s_evJ, s_side);

    // main: join CSR, then serial agg1 -> gemm2 -> agg2
    cudaStreamWaitEvent(0, s_evJ, 0);
    agg1_kernel<<<(n * 32 + 63) / 64, 64>>>(xph, bias1, h1h, n);
    gemm_att_kernel<1><<<ggrid, 256>>>(h1h, wth2, xh,
                                       att_src2, att_dst2, asrc2, adst2, n);
    agg2_kernel<<<(n * 32 + 63) / 64, 64>>>(xh, bias2, bn_gamma, bn_beta, bn_mean,
                                            bn_var, ln_gamma, ln_beta, out, n);
    (void)n_in; (void)out_size;
}

// round 15
// speedup vs baseline: 1.0788x; 1.0788x over previous
#include <cuda_runtime.h>
#include <cuda_fp16.h>
#include <math.h>
#include <stdint.h>

// ---------------- problem constants ----------------
#define NN      50000      // nodes
#define EMAX    800000     // edges (before self loops)
#define ETOT    (EMAX + NN)
#define FEAT    256        // NFEAT = NHEADS*NHID = NOUT = 256
#define NHEADS  4
#define NHID    64
#define NEG_SLOPE 0.2f
#define BN_EPS  1e-5f
#define LN_EPS  1e-5f

// ---------------- scratch (device globals; no runtime alloc) ----------------
// Buffer lifecycle (per call):
//   g_xh : [prep] x->fp16 --(gemm1 reads)--> dead --> [gemm2 writes xp2] --> agg2 gathers
//   g_xph: [gemm1 writes xp1] --> agg1 gathers
//   g_h1h: [agg1 writes] --> gemm2 reads
__device__ __half g_xh[NN * FEAT];
__device__ __half g_xph[NN * FEAT];
__device__ __half g_h1h[NN * FEAT];
__device__ __half g_wth1[FEAT * FEAT];         // W1^T, fp16, [n][k]
__device__ __half g_wth2[FEAT * FEAT];         // W2^T, fp16, [n][k]
__device__ float g_asrc[NN * NHEADS];          // layer-1 logits (per head)
__device__ float g_adst[NN * NHEADS];
__device__ float g_asrc2[NN];                  // layer-2 logits (atomic-accumulated)
__device__ float g_adst2[NN];
__device__ int   g_count[NN];                  // zero at rest (restored by fill_kernel)
__device__ int   g_rowptr[NN + 1];
__device__ int   g_cursor[NN];
__device__ int   g_csrsrc[ETOT];

// ---------------- count + weight transpose + x->fp16 convert, fused (one launch) ----------------
__global__ void prep_kernel(const int* __restrict__ ei, int E, int nblk_e,
                            const float* __restrict__ W1,
                            const float* __restrict__ W2,
                            const float* __restrict__ x, int nx8) {
    if ((int)blockIdx.x < nblk_e) {
        int i = blockIdx.x * blockDim.x + threadIdx.x;
        if (i < E) {
            int d = ei[E + i];      // dst row of edge_index
            atomicAdd(&g_count[d], 1);
        }
        return;
    }
    int tb = blockIdx.x - nblk_e;
    if (tb < 128) {
        __shared__ float tile[32][33];
        int z = tb >> 6;                        // 0 = W1, 1 = W2
        int rem = tb & 63;
        int bx = (rem & 7) * 32, by = (rem >> 3) * 32;
        const float* W  = (z == 0) ? W1 : W2;
        __half* Wt = (z == 0) ? g_wth1 : g_wth2;
        int tx = threadIdx.x & 31, ty = threadIdx.x >> 5;   // 32 x 8
        #pragma unroll
        for (int i = 0; i < 32; i += 8)
            tile[ty + i][tx] = W[(by + ty + i) * FEAT + bx + tx];
        __syncthreads();
        #pragma unroll
        for (int i = 0; i < 32; i += 8)
            Wt[(bx + ty + i) * FEAT + by + tx] = __float2half_rn(tile[tx][ty + i]);
        return;
    }
    int i8 = (tb - 128) * blockDim.x + threadIdx.x;
    if (i8 < nx8) {
        const float4* src = reinterpret_cast<const float4*>(x + (size_t)i8 * 8);
        float4 a = src[0], b = src[1];
        __half2 h0 = __float22half2_rn(make_float2(a.x, a.y));
        __half2 h1 = __float22half2_rn(make_float2(a.z, a.w));
        __half2 h2 = __float22half2_rn(make_float2(b.x, b.y));
        __half2 h3 = __float22half2_rn(make_float2(b.z, b.w));
        uint4 o;
        o.x = *reinterpret_cast<uint32_t*>(&h0);
        o.y = *reinterpret_cast<uint32_t*>(&h1);
        o.z = *reinterpret_cast<uint32_t*>(&h2);
        o.w = *reinterpret_cast<uint32_t*>(&h3);
        *reinterpret_cast<uint4*>(g_xh + (size_t)i8 * 8) = o;
    }
}

// single-block scan, 1024 threads, 4 elements/thread; adds +1 per node (self loop)
__global__ void scan_kernel(int n) {
    __shared__ int warpsum[32];
    __shared__ int s_carry;
    int tid = threadIdx.x, lane = tid & 31, wid = tid >> 5;
    if (tid == 0) { s_carry = 0; g_rowptr[0] = 0; }
    __syncthreads();
    for (int base = 0; base < n; base += 4096) {
        int i = base + tid * 4;
        int v0 = 0, v1 = 0, v2 = 0, v3 = 0;
        if (i + 3 < n) {
            int4 q = *reinterpret_cast<const int4*>(&g_count[i]);
            v0 = q.x + 1; v1 = q.y + 1; v2 = q.z + 1; v3 = q.w + 1;  // +1 self loop
        } else {
            if (i     < n) v0 = g_count[i]     + 1;
            if (i + 1 < n) v1 = g_count[i + 1] + 1;
            if (i + 2 < n) v2 = g_count[i + 2] + 1;
        }
        int t = v0 + v1 + v2 + v3;
        int x = t;
        #pragma unroll
        for (int off = 1; off < 32; off <<= 1) {
            int y = __shfl_up_sync(0xffffffffu, x, off);
            if (lane >= off) x += y;
        }
        if (lane == 31) warpsum[wid] = x;
        __syncthreads();
        int woff = 0, tot = 0;
        #pragma unroll
        for (int w = 0; w < 32; w++) {
            int ws = warpsum[w];
            if (w < wid) woff += ws;
            tot += ws;
        }
        int carry = s_carry;
        int excl = carry + woff + x - t;   // exclusive prefix at element i
        int e1 = excl + v0, e2 = e1 + v1, e3 = e2 + v2;
        if (i     < n) { g_cursor[i]     = excl; g_rowptr[i + 1] = e1; }
        if (i + 1 < n) { g_cursor[i + 1] = e1;   g_rowptr[i + 2] = e2; }
        if (i + 2 < n) { g_cursor[i + 2] = e2;   g_rowptr[i + 3] = e3; }
        if (i + 3 < n) { g_cursor[i + 3] = e3;   g_rowptr[i + 4] = e3 + v3; }
        __syncthreads();
        if (tid == 0) s_carry = carry + tot;
        __syncthreads();
    }
}

// fill also: re-zeros g_count (restores rest state) and zeros asrc2/adst2.
__global__ void fill_kernel(const int* __restrict__ ei, int E, int n) {
    int i = blockIdx.x * blockDim.x + threadIdx.x;
    int tot = E + n;
    if (i >= tot) return;
    int s, d;
    if (i < E) {
        s = ei[i]; d = ei[E + i];
        if (i < n) g_count[i] = 0;
    } else {
        s = d = i - E;
        g_asrc2[d] = 0.f;
        g_adst2[d] = 0.f;
    }
    int pos = atomicAdd(&g_cursor[d], 1);
    g_csrsrc[pos] = s;
}

// ---------------- FP16 tensor-core GEMM (m16n8k16), 128x256 CTA tile, 64x64 warp tile ----------------
// A [M,256] fp16 row-major; Wt [n][k] fp16 (B col-major). CTA covers ALL 256 output cols.
// 8 warps in 2x4 (wm rows, wn cols). BK=32. Dynamic smem, 2-stage cp.async.
#define PH 40                 // smem pitch in halfs (80B = 5x16B, ldmatrix conflict-free)
#define GSTAGE_HALFS ((128 + 256) * PH)     // A rows + B rows per stage
#define GSTAGE_BYTES (GSTAGE_HALFS * 2)     // 30720
#define GSMEM_TOTAL  (2 * GSTAGE_BYTES)     // 61440

__device__ __forceinline__ void ldsm_x4(uint32_t addr, uint32_t& r0, uint32_t& r1,
                                        uint32_t& r2, uint32_t& r3) {
    asm volatile("ldmatrix.sync.aligned.m8n8.x4.shared.b16 {%0,%1,%2,%3}, [%4];"
                 : "=r"(r0), "=r"(r1), "=r"(r2), "=r"(r3) : "r"(addr));
}

__device__ __forceinline__ void mma_fp16(float* c, const uint32_t* a, const uint32_t* b) {
    asm volatile(
        "mma.sync.aligned.m16n8k16.row.col.f32.f16.f16.f32 "
        "{%0,%1,%2,%3}, {%4,%5,%6,%7}, {%8,%9}, {%0,%1,%2,%3};"
        : "+f"(c[0]), "+f"(c[1]), "+f"(c[2]), "+f"(c[3])
        : "r"(a[0]), "r"(a[1]), "r"(a[2]), "r"(a[3]), "r"(b[0]), "r"(b[1]));
}

__device__ __forceinline__ void cp16(uint32_t saddr, const void* gptr, uint32_t srcsize) {
    asm volatile("cp.async.ca.shared.global [%0], [%1], 16, %2;\n"
                 :: "r"(saddr), "l"(gptr), "r"(srcsize));
}

template<int HEADS>
__global__ __launch_bounds__(256, 1) void gemm_att_kernel(
    const __half* __restrict__ A, const __half* __restrict__ Wt,
    __half* __restrict__ Ch,
    const float* __restrict__ attS, const float* __restrict__ attD,
    float* __restrict__ oS, float* __restrict__ oD, int M)
{
    extern __shared__ __half smem[];
    const int K = 256;
    int tid = threadIdx.x;
    int lane = tid & 31;
    int warp = tid >> 5;
    int wm = warp >> 2;          // 0..1 (row group of 64)
    int wn = warp & 3;           // 0..3 (col group of 64)
    int block_row = blockIdx.x * 128;

    uint32_t s_base = (uint32_t)__cvta_generic_to_shared(smem);
    uint32_t sA = s_base;
    uint32_t sB = s_base + 128 * PH * 2;

    // ---- cp.async mapping: A 2 chunks/thread (512 total), B 4 chunks/thread (1024 total) ----
    int ca0 = tid * 2, ca1 = tid * 2 + 1;
    int ar0 = ca0 >> 2, ac0 = (ca0 & 3) * 8;
    int ar1 = ca1 >> 2, ac1 = (ca1 & 3) * 8;
    uint32_t dstA0 = sA + (uint32_t)(ar0 * PH + ac0) * 2;
    uint32_t dstA1 = sA + (uint32_t)(ar1 * PH + ac1) * 2;
    int grA0 = block_row + ar0, grA1 = block_row + ar1;
    uint32_t szA0 = (grA0 < M) ? 16u : 0u;
    uint32_t szA1 = (grA1 < M) ? 16u : 0u;
    if (grA0 >= M) grA0 = 0;
    if (grA1 >= M) grA1 = 0;
    const __half* srcA0 = A + (size_t)grA0 * K + ac0;
    const __half* srcA1 = A + (size_t)grA1 * K + ac1;
    // B: thread t owns weight row t (all 256 rows), 4 chunks of 8 halfs
    uint32_t dstB = sB + (uint32_t)(tid * PH) * 2;
    const __half* srcB = Wt + (size_t)tid * K;

    // ---- ldmatrix per-lane base addresses ----
    int g = lane >> 3, r = lane & 7;
    int a_row_l = (g & 1) * 8 + r;
    int a_koff  = (g >> 1) * 8;
    uint32_t a_base[4];
    #pragma unroll
    for (int mt = 0; mt < 4; mt++)
        a_base[mt] = sA + (uint32_t)((wm * 64 + mt * 16 + a_row_l) * PH + a_koff) * 2;
    int b_row_l = (g >> 1) * 8 + r;
    int b_koff  = (g & 1) * 8;
    uint32_t b_base[4];
    #pragma unroll
    for (int np = 0; np < 4; np++)
        b_base[np] = sB + (uint32_t)((wn * 64 + np * 16 + b_row_l) * PH + b_koff) * 2;

    float acc[4][8][4];
    #pragma unroll
    for (int mt = 0; mt < 4; mt++)
        #pragma unroll
        for (int nt = 0; nt < 8; nt++)
            #pragma unroll
            for (int q = 0; q < 4; q++) acc[mt][nt][q] = 0.f;

    cp16(dstA0, srcA0, szA0);
    cp16(dstA1, srcA1, szA1);
    #pragma unroll
    for (int j = 0; j < 4; j++)
        cp16(dstB + (uint32_t)(j * 8) * 2, srcB + j * 8, 16u);
    asm volatile("cp.async.commit_group;\n" ::);

    const int NITER = K / 32;   // 8
    for (int it = 0; it < NITER; it++) {
        int buf = it & 1;
        if (it + 1 < NITER) {
            uint32_t off = ((it + 1) & 1) * GSTAGE_BYTES;
            int k0 = (it + 1) * 32;
            cp16(dstA0 + off, srcA0 + k0, szA0);
            cp16(dstA1 + off, srcA1 + k0, szA1);
            #pragma unroll
            for (int j = 0; j < 4; j++)
                cp16(dstB + off + (uint32_t)(j * 8) * 2, srcB + k0 + j * 8, 16u);
            asm volatile("cp.async.commit_group;\n" ::);
            asm volatile("cp.async.wait_group 1;\n" ::);
        } else {
            asm volatile("cp.async.wait_group 0;\n" ::);
        }
        __syncthreads();

        uint32_t soff = buf * GSTAGE_BYTES;
        #pragma unroll
        for (int ks = 0; ks < 32; ks += 16) {
            uint32_t a[4][4], b[4][4];
            #pragma unroll
            for (int mt = 0; mt < 4; mt++)
                ldsm_x4(a_base[mt] + soff + ks * 2, a[mt][0], a[mt][1], a[mt][2], a[mt][3]);
            #pragma unroll
            for (int np = 0; np < 4; np++)
                ldsm_x4(b_base[np] + soff + ks * 2, b[np][0], b[np][1], b[np][2], b[np][3]);
            #pragma unroll
            for (int mt = 0; mt < 4; mt++)
                #pragma unroll
                for (int nt = 0; nt < 8; nt++)
                    mma_fp16(acc[mt][nt], a[mt], &b[nt >> 1][(nt & 1) * 2]);
        }
        __syncthreads();
    }

    // ---- epilogue: fp16 stores ----
    int cr = lane >> 2;
    int cc = (lane & 3) * 2;
    #pragma unroll
    for (int mt = 0; mt < 4; mt++) {
        int row0 = block_row + wm * 64 + mt * 16 + cr;
        #pragma unroll
        for (int nt = 0; nt < 8; nt++) {
            int col = wn * 64 + nt * 8 + cc;
            if (row0 < M)
                *reinterpret_cast<__half2*>(Ch + (size_t)row0 * 256 + col) =
                    __float22half2_rn(make_float2(acc[mt][nt][0], acc[mt][nt][1]));
            if (row0 + 8 < M)
                *reinterpret_cast<__half2*>(Ch + (size_t)(row0 + 8) * 256 + col) =
                    __float22half2_rn(make_float2(acc[mt][nt][2], acc[mt][nt][3]));
        }
    }

    // ---- epilogue: fused attention-logit partial dots over this warp's 64 cols ----
    // HEADS=4: warp's col group wn IS head wn (attS layout [4][64] == flat 256).
    float ps[4][2] = {{0.f,0.f},{0.f,0.f},{0.f,0.f},{0.f,0.f}};
    float pd[4][2] = {{0.f,0.f},{0.f,0.f},{0.f,0.f},{0.f,0.f}};
    #pragma unroll
    for (int mt = 0; mt < 4; mt++) {
        #pragma unroll
        for (int nt = 0; nt < 8; nt++) {
            int idx = wn * 64 + nt * 8 + cc;
            float as0 = attS[idx], as1 = attS[idx + 1];
            float ad0 = attD[idx], ad1 = attD[idx + 1];
            ps[mt][0] += acc[mt][nt][0] * as0 + acc[mt][nt][1] * as1;
            ps[mt][1] += acc[mt][nt][2] * as0 + acc[mt][nt][3] * as1;
            pd[mt][0] += acc[mt][nt][0] * ad0 + acc[mt][nt][1] * ad1;
            pd[mt][1] += acc[mt][nt][2] * ad0 + acc[mt][nt][3] * ad1;
        }
    }
    #pragma unroll
    for (int mt = 0; mt < 4; mt++)
        #pragma unroll
        for (int hf = 0; hf < 2; hf++) {
            ps[mt][hf] += __shfl_xor_sync(0xffffffffu, ps[mt][hf], 1);
            ps[mt][hf] += __shfl_xor_sync(0xffffffffu, ps[mt][hf], 2);
            pd[mt][hf] += __shfl_xor_sync(0xffffffffu, pd[mt][hf], 1);
            pd[mt][hf] += __shfl_xor_sync(0xffffffffu, pd[mt][hf], 2);
        }
    if ((lane & 3) == 0) {
        #pragma unroll
        for (int mt = 0; mt < 4; mt++)
            #pragma unroll
            for (int hf = 0; hf < 2; hf++) {
                int node = block_row + wm * 64 + mt * 16 + cr + hf * 8;
                if (node < M) {
                    if (HEADS == 4) {
                        oS[node * 4 + wn] = ps[mt][hf];
                        oD[node * 4 + wn] = pd[mt][hf];
                    } else {
                        atomicAdd(&oS[node], ps[mt][hf]);
                        atomicAdd(&oD[node], pd[mt][hf]);
                    }
                }
            }
    }
}

__device__ __forceinline__ float leaky(float x) {
    return (x > 0.f) ? x : NEG_SLOPE * x;
}

__device__ __forceinline__ void unpack8h(uint4 u, float* f) {
    float2 a = __half22float2(*reinterpret_cast<__half2*>(&u.x));
    float2 b = __half22float2(*reinterpret_cast<__half2*>(&u.y));
    float2 c = __half22float2(*reinterpret_cast<__half2*>(&u.z));
    float2 d = __half22float2(*reinterpret_cast<__half2*>(&u.w));
    f[0] = a.x; f[1] = a.y; f[2] = b.x; f[3] = b.y;
    f[4] = c.x; f[5] = c.y; f[6] = d.x; f[7] = d.y;
}

__device__ __forceinline__ uint4 pack8h(const float* f) {
    __half2 h0 = __float22half2_rn(make_float2(f[0], f[1]));
    __half2 h1 = __float22half2_rn(make_float2(f[2], f[3]));
    __half2 h2 = __float22half2_rn(make_float2(f[4], f[5]));
    __half2 h3 = __float22half2_rn(make_float2(f[6], f[7]));
    uint4 o;
    o.x = *reinterpret_cast<uint32_t*>(&h0);
    o.y = *reinterpret_cast<uint32_t*>(&h1);
    o.z = *reinterpret_cast<uint32_t*>(&h2);
    o.w = *reinterpret_cast<uint32_t*>(&h3);
    return o;
}

// ---------------- aggregation, layer 1 (4 heads, fp16 gather) + bias + ELU -> fp16 h1 ----------------
__global__ __launch_bounds__(64) void agg1_kernel(const __half* __restrict__ xph,
                            const float* __restrict__ bias,
                            __half* __restrict__ out, int n)
{
    int node = (blockIdx.x * blockDim.x + threadIdx.x) >> 5;
    if (node >= n) return;
    int lane = threadIdx.x & 31;
    int h  = lane >> 3;         // 8 lanes per head
    int c0 = lane * 8;
    float ad = g_adst[node * NHEADS + h];
    int beg = g_rowptr[node], end = g_rowptr[node + 1];
    float m = -1e30f, s = 0.f;
    float acc[8] = {0,0,0,0,0,0,0,0};
    int p = beg;
    for (; p + 1 < end; p += 2) {
        int j0 = g_csrsrc[p];
        int j1 = g_csrsrc[p + 1];
        float e0 = leaky(g_asrc[j0 * NHEADS + h] + ad);
        float e1 = leaky(g_asrc[j1 * NHEADS + h] + ad);
        uint4 u0 = *reinterpret_cast<const uint4*>(xph + (size_t)j0 * FEAT + c0);
        uint4 u1 = *reinterpret_cast<const uint4*>(xph + (size_t)j1 * FEAT + c0);
        float fa[8], fb[8];
        unpack8h(u0, fa);
        unpack8h(u1, fb);
        float mn = fmaxf(m, fmaxf(e0, e1));
        float corr = __expf(m - mn);
        float p0   = __expf(e0 - mn);
        float p1   = __expf(e1 - mn);
        s = s * corr + p0 + p1;
        #pragma unroll
        for (int k = 0; k < 8; k++)
            acc[k] = acc[k] * corr + p0 * fa[k] + p1 * fb[k];
        m = mn;
    }
    if (p < end) {
        int j = g_csrsrc[p];
        float e = leaky(g_asrc[j * NHEADS + h] + ad);
        uint4 u = *reinterpret_cast<const uint4*>(xph + (size_t)j * FEAT + c0);
        float fa[8];
        unpack8h(u, fa);
        float mn = fmaxf(m, e);
        float corr = __expf(m - mn);
        float pw   = __expf(e - mn);
        s = s * corr + pw;
        #pragma unroll
        for (int k = 0; k < 8; k++)
            acc[k] = acc[k] * corr + pw * fa[k];
    }
    float inv = 1.f / s;
    const float4* b4 = reinterpret_cast<const float4*>(bias + c0);
    float4 bb0 = b4[0], bb1 = b4[1];
    float vb[8] = {bb0.x, bb0.y, bb0.z, bb0.w, bb1.x, bb1.y, bb1.z, bb1.w};
    float v[8];
    #pragma unroll
    for (int k = 0; k < 8; k++) {
        float t = acc[k] * inv + vb[k];
        v[k] = (t > 0.f) ? t : expm1f(t);   // ELU
    }
    *reinterpret_cast<uint4*>(out + (size_t)node * FEAT + c0) = pack8h(v);
}

// ---------------- aggregation, layer 2 (1 head, fp16 gather) + bias + ELU + BN + LN ----------------
__global__ __launch_bounds__(64) void agg2_kernel(const __half* __restrict__ xp2,
                            const float* __restrict__ bias,
                            const float* __restrict__ bn_gamma,
                            const float* __restrict__ bn_beta,
                            const float* __restrict__ bn_mean,
                            const float* __restrict__ bn_var,
                            const float* __restrict__ ln_gamma,
                            const float* __restrict__ ln_beta,
                            float* __restrict__ out, int n)
{
    int node = (blockIdx.x * blockDim.x + threadIdx.x) >> 5;
    if (node >= n) return;
    int lane = threadIdx.x & 31;
    int c0 = lane * 8;
    float ad = g_adst2[node];
    int beg = g_rowptr[node], end = g_rowptr[node + 1];
    float m = -1e30f, s = 0.f;
    float acc[8] = {0,0,0,0,0,0,0,0};
    int p = beg;
    for (; p + 1 < end; p += 2) {
        int j0 = g_csrsrc[p];
        int j1 = g_csrsrc[p + 1];
        float e0 = leaky(g_asrc2[j0] + ad);
        float e1 = leaky(g_asrc2[j1] + ad);
        uint4 u0 = *reinterpret_cast<const uint4*>(xp2 + (size_t)j0 * FEAT + c0);
        uint4 u1 = *reinterpret_cast<const uint4*>(xp2 + (size_t)j1 * FEAT + c0);
        float fa[8], fb[8];
        unpack8h(u0, fa);
        unpack8h(u1, fb);
        float mn = fmaxf(m, fmaxf(e0, e1));
        float corr = __expf(m - mn);
        float p0   = __expf(e0 - mn);
        float p1   = __expf(e1 - mn);
        s = s * corr + p0 + p1;
        #pragma unroll
        for (int k = 0; k < 8; k++)
            acc[k] = acc[k] * corr + p0 * fa[k] + p1 * fb[k];
        m = mn;
    }
    if (p < end) {
        int j = g_csrsrc[p];
        float e = leaky(g_asrc2[j] + ad);
        uint4 u = *reinterpret_cast<const uint4*>(xp2 + (size_t)j * FEAT + c0);
        float fa[8];
        unpack8h(u, fa);
        float mn = fmaxf(m, e);
        float corr = __expf(m - mn);
        float pw   = __expf(e - mn);
        s = s * corr + pw;
        #pragma unroll
        for (int k = 0; k < 8; k++)
            acc[k] = acc[k] * corr + pw * fa[k];
    }
    float inv = 1.f / s;
    float v[8];
    #pragma unroll
    for (int k = 0; k < 8; k++) {
        int c = c0 + k;
        float x = acc[k] * inv + bias[c];
        x = (x > 0.f) ? x : expm1f(x);                           // ELU
        x = (x - bn_mean[c]) * rsqrtf(bn_var[c] + BN_EPS) * bn_gamma[c] + bn_beta[c];  // BN eval
        v[k] = x;
    }
    // LayerNorm over 256 channels (warp = row, 8 ch/lane)
    float lsum = 0.f;
    #pragma unroll
    for (int k = 0; k < 8; k++) lsum += v[k];
    #pragma unroll
    for (int off = 16; off; off >>= 1) lsum += __shfl_xor_sync(0xffffffffu, lsum, off);
    float mu = lsum * (1.f / 256.f);
    float lvar = 0.f;
    #pragma unroll
    for (int k = 0; k < 8; k++) { float d = v[k] - mu; lvar += d * d; }
    #pragma unroll
    for (int off = 16; off; off >>= 1) lvar += __shfl_xor_sync(0xffffffffu, lvar, off);
    float r = rsqrtf(lvar * (1.f / 256.f) + LN_EPS);
    float w[8];
    #pragma unroll
    for (int k = 0; k < 8; k++) {
        int c = c0 + k;
        w[k] = (v[k] - mu) * r * ln_gamma[c] + ln_beta[c];
    }
    float4 o0 = make_float4(w[0], w[1], w[2], w[3]);
    float4 o1 = make_float4(w[4], w[5], w[6], w[7]);
    float4* orow = reinterpret_cast<float4*>(out + (size_t)node * FEAT + c0);
    orow[0] = o0; orow[1] = o1;
}

// ---------------- launch ----------------
extern "C" void kernel_launch(void* const* d_in, const int* in_sizes, int n_in,
                              void* d_out, int out_size)
{
    const float* x        = (const float*)d_in[0];
    const int*   ei       = (const int*)  d_in[1];
    const float* W1       = (const float*)d_in[2];
    const float* att_src1 = (const float*)d_in[3];
    const float* att_dst1 = (const float*)d_in[4];
    const float* bias1    = (const float*)d_in[5];
    const float* W2       = (const float*)d_in[6];
    const float* att_src2 = (const float*)d_in[7];
    const float* att_dst2 = (const float*)d_in[8];
    const float* bias2    = (const float*)d_in[9];
    const float* bn_gamma = (const float*)d_in[10];
    const float* bn_beta  = (const float*)d_in[11];
    const float* bn_mean  = (const float*)d_in[12];
    const float* bn_var   = (const float*)d_in[13];
    const float* ln_gamma = (const float*)d_in[14];
    const float* ln_beta  = (const float*)d_in[15];
    float* out = (float*)d_out;

    int n = in_sizes[0] / FEAT;      // 50000
    int E = in_sizes[1] / 2;         // 800000
    if (n > NN) n = NN;
    if (E > EMAX) E = EMAX;

    float *asrc, *adst, *asrc2, *adst2;
    __half *xh, *xph, *h1h, *wth1, *wth2;
    cudaGetSymbolAddress((void**)&xh,    g_xh);
    cudaGetSymbolAddress((void**)&xph,   g_xph);
    cudaGetSymbolAddress((void**)&h1h,   g_h1h);
    cudaGetSymbolAddress((void**)&wth1,  g_wth1);
    cudaGetSymbolAddress((void**)&wth2,  g_wth2);
    cudaGetSymbolAddress((void**)&asrc,  g_asrc);
    cudaGetSymbolAddress((void**)&adst,  g_adst);
    cudaGetSymbolAddress((void**)&asrc2, g_asrc2);
    cudaGetSymbolAddress((void**)&adst2, g_adst2);

    // lazy side-stream / event creation + smem attribute (outside graph capture on first call)
    static cudaStream_t s_side = nullptr;
    static cudaEvent_t  s_evF = nullptr, s_evW = nullptr, s_evJ = nullptr;
    if (s_side == nullptr) {
        cudaStreamCreateWithFlags(&s_side, cudaStreamNonBlocking);
        cudaEventCreateWithFlags(&s_evF, cudaEventDisableTiming);
        cudaEventCreateWithFlags(&s_evW, cudaEventDisableTiming);
        cudaEventCreateWithFlags(&s_evJ, cudaEventDisableTiming);
        cudaFuncSetAttribute(gemm_att_kernel<4>,
                             cudaFuncAttributeMaxDynamicSharedMemorySize, GSMEM_TOTAL);
        cudaFuncSetAttribute(gemm_att_kernel<1>,
                             cudaFuncAttributeMaxDynamicSharedMemorySize, GSMEM_TOTAL);
    }

    // --- fork: prep (count+transpose+convert) on side stream, then scan+fill overlap gemm1 ---
    cudaEventRecord(s_evF, 0);
    cudaStreamWaitEvent(s_side, s_evF, 0);
    int nblk_e = (E + 255) / 256;
    int nx8 = n * FEAT / 8;
    int nblk_x = (nx8 + 255) / 256;
    prep_kernel<<<nblk_e + 128 + nblk_x, 256, 0, s_side>>>(ei, E, nblk_e, W1, W2, x, nx8);  // 1
    cudaEventRecord(s_evW, s_side);
    scan_kernel<<<1, 1024, 0, s_side>>>(n);                                                 // 2
    fill_kernel<<<(E + n + 255) / 256, 256, 0, s_side>>>(ei, E, n);                         // 3
    cudaEventRecord(s_evJ, s_side);

    // --- main: layer-1 GEMM (waits on prep; overlaps scan+fill) ---
    cudaStreamWaitEvent(0, s_evW, 0);
    dim3 ggrid((n + 127) / 128, 1);
    gemm_att_kernel<4><<<ggrid, 256, GSMEM_TOTAL>>>(xh, wth1, xph,                          // 4 (profiled)
                                                    att_src1, att_dst1, asrc, adst, n);

    // --- join: CSR ready; serial agg1 -> gemm2 -> agg2 ---
    cudaStreamWaitEvent(0, s_evJ, 0);
    agg1_kernel<<<(n * 32 + 63) / 64, 64>>>(xph, bias1, h1h, n);
    gemm_att_kernel<1><<<ggrid, 256, GSMEM_TOTAL>>>(h1h, wth2, xh,
                                                    att_src2, att_dst2, asrc2, adst2, n);
    agg2_kernel<<<(n * 32 + 63) / 64, 64>>>(xh, bias2, bn_gamma, bn_beta, bn_mean,
                                            bn_var, ln_gamma, ln_beta, out, n);
    (void)n_in; (void)out_size;
}

// round 16
// speedup vs baseline: 1.1073x; 1.0264x over previous
#include <cuda_runtime.h>
#include <cuda_fp16.h>
#include <math.h>
#include <stdint.h>

// ---------------- problem constants ----------------
#define NN      50000      // nodes
#define EMAX    800000     // edges (before self loops)
#define ETOT    (EMAX + NN)
#define FEAT    256        // NFEAT = NHEADS*NHID = NOUT = 256
#define NHEADS  4
#define NHID    64
#define NEG_SLOPE 0.2f
#define BN_EPS  1e-5f
#define LN_EPS  1e-5f

// ---------------- scratch (device globals; no runtime alloc) ----------------
// Buffer lifecycle (per call):
//   g_xh : [prep] x->fp16 --(gemm1 reads)--> dead --> [gemm2 writes xp2] --> agg2 gathers
//   g_xph: [gemm1 writes xp1] --> agg1 gathers
//   g_h1h: [agg1 writes] --> gemm2 reads
__device__ __half g_xh[NN * FEAT];
__device__ __half g_xph[NN * FEAT];
__device__ __half g_h1h[NN * FEAT];
__device__ __half g_wth1[FEAT * FEAT];         // W1^T, fp16, [n][k]
__device__ __half g_wth2[FEAT * FEAT];         // W2^T, fp16, [n][k]
__device__ float g_asrc[NN * NHEADS];          // layer-1 logits (per head)
__device__ float g_adst[NN * NHEADS];
__device__ float g_asrc2[NN];                  // layer-2 logits (atomic-accumulated)
__device__ float g_adst2[NN];
__device__ int   g_count[NN];                  // zero at rest (restored by fill_kernel)
__device__ int   g_rowptr[NN + 1];
__device__ int   g_cursor[NN];
__device__ int   g_csrsrc[ETOT];

// ---------------- count + weight transpose + x->fp16 convert, fused (one launch) ----------------
__global__ void prep_kernel(const int* __restrict__ ei, int E, int nblk_e,
                            const float* __restrict__ W1,
                            const float* __restrict__ W2,
                            const float* __restrict__ x, int nx8) {
    if ((int)blockIdx.x < nblk_e) {
        int i = blockIdx.x * blockDim.x + threadIdx.x;
        if (i < E) {
            int d = ei[E + i];      // dst row of edge_index
            atomicAdd(&g_count[d], 1);
        }
        return;
    }
    int tb = blockIdx.x - nblk_e;
    if (tb < 128) {
        __shared__ float tile[32][33];
        int z = tb >> 6;                        // 0 = W1, 1 = W2
        int rem = tb & 63;
        int bx = (rem & 7) * 32, by = (rem >> 3) * 32;
        const float* W  = (z == 0) ? W1 : W2;
        __half* Wt = (z == 0) ? g_wth1 : g_wth2;
        int tx = threadIdx.x & 31, ty = threadIdx.x >> 5;   // 32 x 8
        #pragma unroll
        for (int i = 0; i < 32; i += 8)
            tile[ty + i][tx] = W[(by + ty + i) * FEAT + bx + tx];
        __syncthreads();
        #pragma unroll
        for (int i = 0; i < 32; i += 8)
            Wt[(bx + ty + i) * FEAT + by + tx] = __float2half_rn(tile[tx][ty + i]);
        return;
    }
    int i8 = (tb - 128) * blockDim.x + threadIdx.x;
    if (i8 < nx8) {
        const float4* src = reinterpret_cast<const float4*>(x + (size_t)i8 * 8);
        float4 a = src[0], b = src[1];
        __half2 h0 = __float22half2_rn(make_float2(a.x, a.y));
        __half2 h1 = __float22half2_rn(make_float2(a.z, a.w));
        __half2 h2 = __float22half2_rn(make_float2(b.x, b.y));
        __half2 h3 = __float22half2_rn(make_float2(b.z, b.w));
        uint4 o;
        o.x = *reinterpret_cast<uint32_t*>(&h0);
        o.y = *reinterpret_cast<uint32_t*>(&h1);
        o.z = *reinterpret_cast<uint32_t*>(&h2);
        o.w = *reinterpret_cast<uint32_t*>(&h3);
        *reinterpret_cast<uint4*>(g_xh + (size_t)i8 * 8) = o;
    }
}

// single-block scan, 1024 threads, 4 elements/thread; adds +1 per node (self loop)
__global__ void scan_kernel(int n) {
    __shared__ int warpsum[32];
    __shared__ int s_carry;
    int tid = threadIdx.x, lane = tid & 31, wid = tid >> 5;
    if (tid == 0) { s_carry = 0; g_rowptr[0] = 0; }
    __syncthreads();
    for (int base = 0; base < n; base += 4096) {
        int i = base + tid * 4;
        int v0 = 0, v1 = 0, v2 = 0, v3 = 0;
        if (i + 3 < n) {
            int4 q = *reinterpret_cast<const int4*>(&g_count[i]);
            v0 = q.x + 1; v1 = q.y + 1; v2 = q.z + 1; v3 = q.w + 1;  // +1 self loop
        } else {
            if (i     < n) v0 = g_count[i]     + 1;
            if (i + 1 < n) v1 = g_count[i + 1] + 1;
            if (i + 2 < n) v2 = g_count[i + 2] + 1;
        }
        int t = v0 + v1 + v2 + v3;
        int x = t;
        #pragma unroll
        for (int off = 1; off < 32; off <<= 1) {
            int y = __shfl_up_sync(0xffffffffu, x, off);
            if (lane >= off) x += y;
        }
        if (lane == 31) warpsum[wid] = x;
        __syncthreads();
        int woff = 0, tot = 0;
        #pragma unroll
        for (int w = 0; w < 32; w++) {
            int ws = warpsum[w];
            if (w < wid) woff += ws;
            tot += ws;
        }
        int carry = s_carry;
        int excl = carry + woff + x - t;   // exclusive prefix at element i
        int e1 = excl + v0, e2 = e1 + v1, e3 = e2 + v2;
        if (i     < n) { g_cursor[i]     = excl; g_rowptr[i + 1] = e1; }
        if (i + 1 < n) { g_cursor[i + 1] = e1;   g_rowptr[i + 2] = e2; }
        if (i + 2 < n) { g_cursor[i + 2] = e2;   g_rowptr[i + 3] = e3; }
        if (i + 3 < n) { g_cursor[i + 3] = e3;   g_rowptr[i + 4] = e3 + v3; }
        __syncthreads();
        if (tid == 0) s_carry = carry + tot;
        __syncthreads();
    }
}

// fill also: re-zeros g_count (restores rest state) and zeros asrc2/adst2.
__global__ void fill_kernel(const int* __restrict__ ei, int E, int n) {
    int i = blockIdx.x * blockDim.x + threadIdx.x;
    int tot = E + n;
    if (i >= tot) return;
    int s, d;
    if (i < E) {
        s = ei[i]; d = ei[E + i];
        if (i < n) g_count[i] = 0;
    } else {
        s = d = i - E;
        g_asrc2[d] = 0.f;
        g_adst2[d] = 0.f;
    }
    int pos = atomicAdd(&g_cursor[d], 1);
    g_csrsrc[pos] = s;
}

// ---------------- FP16 tensor-core GEMM (m16n8k16), 128x128 CTA, 32x64 warp tile, 3-stage ----------------
#define PH 40                 // smem pitch in halfs (80B = 5x16B, ldmatrix conflict-free)
#define STAGE_BYTES (2 * 128 * PH * 2)   // As + Bs per stage = 20480
#define GSMEM_TOTAL (3 * STAGE_BYTES)    // 61440

__device__ __forceinline__ void ldsm_x4(uint32_t addr, uint32_t& r0, uint32_t& r1,
                                        uint32_t& r2, uint32_t& r3) {
    asm volatile("ldmatrix.sync.aligned.m8n8.x4.shared.b16 {%0,%1,%2,%3}, [%4];"
                 : "=r"(r0), "=r"(r1), "=r"(r2), "=r"(r3) : "r"(addr));
}

__device__ __forceinline__ void mma_fp16(float* c, const uint32_t* a, const uint32_t* b) {
    asm volatile(
        "mma.sync.aligned.m16n8k16.row.col.f32.f16.f16.f32 "
        "{%0,%1,%2,%3}, {%4,%5,%6,%7}, {%8,%9}, {%0,%1,%2,%3};"
        : "+f"(c[0]), "+f"(c[1]), "+f"(c[2]), "+f"(c[3])
        : "r"(a[0]), "r"(a[1]), "r"(a[2]), "r"(a[3]), "r"(b[0]), "r"(b[1]));
}

__device__ __forceinline__ void cp16(uint32_t saddr, const void* gptr, uint32_t srcsize) {
    asm volatile("cp.async.ca.shared.global [%0], [%1], 16, %2;\n"
                 :: "r"(saddr), "l"(gptr), "r"(srcsize));
}

template<int HEADS>
__global__ __launch_bounds__(256) void gemm_att_kernel(
    const __half* __restrict__ A, const __half* __restrict__ Wt,
    __half* __restrict__ Ch,
    const float* __restrict__ attS, const float* __restrict__ attD,
    float* __restrict__ oS, float* __restrict__ oD, int M)
{
    extern __shared__ __half smem[];
    const int K = 256;
    int tid = threadIdx.x;
    int lane = tid & 31;
    int warp = tid >> 5;
    int wm = warp >> 1;          // 0..3
    int wn = warp & 1;           // 0..1
    int block_row = blockIdx.x * 128;
    int block_col = blockIdx.y * 128;

    uint32_t s_base = (uint32_t)__cvta_generic_to_shared(smem);
    uint32_t sA = s_base;
    uint32_t sB = s_base + 128 * PH * 2;

    int c0i = tid * 2, c1i = tid * 2 + 1;
    int ar0 = c0i >> 2, ac0 = (c0i & 3) * 8;   // col offset in halfs
    int ar1 = c1i >> 2, ac1 = (c1i & 3) * 8;
    uint32_t dstA0 = sA + (uint32_t)(ar0 * PH + ac0) * 2;
    uint32_t dstA1 = sA + (uint32_t)(ar1 * PH + ac1) * 2;
    uint32_t dstB0 = sB + (uint32_t)(ar0 * PH + ac0) * 2;
    uint32_t dstB1 = sB + (uint32_t)(ar1 * PH + ac1) * 2;
    int grA0 = block_row + ar0, grA1 = block_row + ar1;
    uint32_t szA0 = (grA0 < M) ? 16u : 0u;
    uint32_t szA1 = (grA1 < M) ? 16u : 0u;
    if (grA0 >= M) grA0 = 0;
    if (grA1 >= M) grA1 = 0;
    const __half* srcA0 = A + (size_t)grA0 * K + ac0;
    const __half* srcA1 = A + (size_t)grA1 * K + ac1;
    const __half* srcB0 = Wt + (size_t)(block_col + ar0) * K + ac0;
    const __half* srcB1 = Wt + (size_t)(block_col + ar1) * K + ac1;

    int g = lane >> 3, r = lane & 7;
    int a_row_l = (g & 1) * 8 + r;
    int a_koff  = (g >> 1) * 8;                // halfs
    uint32_t a_base[2];
    #pragma unroll
    for (int mt = 0; mt < 2; mt++)
        a_base[mt] = sA + (uint32_t)((wm * 32 + mt * 16 + a_row_l) * PH + a_koff) * 2;
    int b_row_l = (g >> 1) * 8 + r;
    int b_koff  = (g & 1) * 8;                 // halfs
    uint32_t b_base[4];
    #pragma unroll
    for (int np = 0; np < 4; np++)
        b_base[np] = sB + (uint32_t)((wn * 64 + np * 16 + b_row_l) * PH + b_koff) * 2;

    float acc[2][8][4];
    #pragma unroll
    for (int mt = 0; mt < 2; mt++)
        #pragma unroll
        for (int nt = 0; nt < 8; nt++)
            #pragma unroll
            for (int q = 0; q < 4; q++) acc[mt][nt][q] = 0.f;

    // ---- prologue: stages 0 and 1 ----
    const int NITER = K / 32;   // 8
    #pragma unroll
    for (int st = 0; st < 2; st++) {
        uint32_t off = st * STAGE_BYTES;
        int k0 = st * 32;
        cp16(dstA0 + off, srcA0 + k0, szA0);
        cp16(dstA1 + off, srcA1 + k0, szA1);
        cp16(dstB0 + off, srcB0 + k0, 16u);
        cp16(dstB1 + off, srcB1 + k0, 16u);
        asm volatile("cp.async.commit_group;\n" ::);
    }

    int buf = 0;
    for (int it = 0; it < NITER; it++) {
        if (it + 2 < NITER) {
            int nb = buf + 2; if (nb >= 3) nb -= 3;
            uint32_t off = (uint32_t)nb * STAGE_BYTES;
            int k0 = (it + 2) * 32;
            cp16(dstA0 + off, srcA0 + k0, szA0);
            cp16(dstA1 + off, srcA1 + k0, szA1);
            cp16(dstB0 + off, srcB0 + k0, 16u);
            cp16(dstB1 + off, srcB1 + k0, 16u);
            asm volatile("cp.async.commit_group;\n" ::);
            asm volatile("cp.async.wait_group 2;\n" ::);
        } else if (it + 1 < NITER) {
            asm volatile("cp.async.wait_group 1;\n" ::);
        } else {
            asm volatile("cp.async.wait_group 0;\n" ::);
        }
        __syncthreads();

        uint32_t soff = (uint32_t)buf * STAGE_BYTES;
        #pragma unroll
        for (int ks = 0; ks < 32; ks += 16) {   // two k16 steps per stage
            uint32_t a[2][4], b[4][4];
            #pragma unroll
            for (int mt = 0; mt < 2; mt++)
                ldsm_x4(a_base[mt] + soff + ks * 2, a[mt][0], a[mt][1], a[mt][2], a[mt][3]);
            #pragma unroll
            for (int np = 0; np < 4; np++)
                ldsm_x4(b_base[np] + soff + ks * 2, b[np][0], b[np][1], b[np][2], b[np][3]);
            #pragma unroll
            for (int mt = 0; mt < 2; mt++)
                #pragma unroll
                for (int nt = 0; nt < 8; nt++)
                    mma_fp16(acc[mt][nt], a[mt], &b[nt >> 1][(nt & 1) * 2]);
        }
        __syncthreads();
        buf++; if (buf >= 3) buf = 0;
    }

    // ---- epilogue: fp16 stores ----
    int cr = lane >> 2;
    int cc = (lane & 3) * 2;
    #pragma unroll
    for (int mt = 0; mt < 2; mt++) {
        int row0 = block_row + wm * 32 + mt * 16 + cr;
        #pragma unroll
        for (int nt = 0; nt < 8; nt++) {
            int col = block_col + wn * 64 + nt * 8 + cc;
            if (row0 < M)
                *reinterpret_cast<__half2*>(Ch + (size_t)row0 * 256 + col) =
                    __float22half2_rn(make_float2(acc[mt][nt][0], acc[mt][nt][1]));
            if (row0 + 8 < M)
                *reinterpret_cast<__half2*>(Ch + (size_t)(row0 + 8) * 256 + col) =
                    __float22half2_rn(make_float2(acc[mt][nt][2], acc[mt][nt][3]));
        }
    }

    // ---- epilogue: fused attention-logit partial dots over this warp's 64 cols ----
    float ps[2][2] = {{0.f,0.f},{0.f,0.f}};
    float pd[2][2] = {{0.f,0.f},{0.f,0.f}};
    #pragma unroll
    for (int mt = 0; mt < 2; mt++) {
        #pragma unroll
        for (int nt = 0; nt < 8; nt++) {
            int lc = nt * 8 + cc;
            int idx = (HEADS == 4) ? ((blockIdx.y * 2 + wn) * 64 + lc)
                                   : (block_col + wn * 64 + lc);
            float as0 = attS[idx], as1 = attS[idx + 1];
            float ad0 = attD[idx], ad1 = attD[idx + 1];
            ps[mt][0] += acc[mt][nt][0] * as0 + acc[mt][nt][1] * as1;
            ps[mt][1] += acc[mt][nt][2] * as0 + acc[mt][nt][3] * as1;
            pd[mt][0] += acc[mt][nt][0] * ad0 + acc[mt][nt][1] * ad1;
            pd[mt][1] += acc[mt][nt][2] * ad0 + acc[mt][nt][3] * ad1;
        }
    }
    #pragma unroll
    for (int mt = 0; mt < 2; mt++)
        #pragma unroll
        for (int hf = 0; hf < 2; hf++) {
            ps[mt][hf] += __shfl_xor_sync(0xffffffffu, ps[mt][hf], 1);
            ps[mt][hf] += __shfl_xor_sync(0xffffffffu, ps[mt][hf], 2);
            pd[mt][hf] += __shfl_xor_sync(0xffffffffu, pd[mt][hf], 1);
            pd[mt][hf] += __shfl_xor_sync(0xffffffffu, pd[mt][hf], 2);
        }
    if ((lane & 3) == 0) {
        #pragma unroll
        for (int mt = 0; mt < 2; mt++)
            #pragma unroll
            for (int hf = 0; hf < 2; hf++) {
                int node = block_row + wm * 32 + mt * 16 + cr + hf * 8;
                if (node < M) {
                    if (HEADS == 4) {
                        int head = blockIdx.y * 2 + wn;
                        oS[node * 4 + head] = ps[mt][hf];
                        oD[node * 4 + head] = pd[mt][hf];
                    } else {
                        atomicAdd(&oS[node], ps[mt][hf]);
                        atomicAdd(&oD[node], pd[mt][hf]);
                    }
                }
            }
    }
}

__device__ __forceinline__ float leaky(float x) {
    return (x > 0.f) ? x : NEG_SLOPE * x;
}

__device__ __forceinline__ void unpack8h(uint4 u, float* f) {
    float2 a = __half22float2(*reinterpret_cast<__half2*>(&u.x));
    float2 b = __half22float2(*reinterpret_cast<__half2*>(&u.y));
    float2 c = __half22float2(*reinterpret_cast<__half2*>(&u.z));
    float2 d = __half22float2(*reinterpret_cast<__half2*>(&u.w));
    f[0] = a.x; f[1] = a.y; f[2] = b.x; f[3] = b.y;
    f[4] = c.x; f[5] = c.y; f[6] = d.x; f[7] = d.y;
}

__device__ __forceinline__ uint4 pack8h(const float* f) {
    __half2 h0 = __float22half2_rn(make_float2(f[0], f[1]));
    __half2 h1 = __float22half2_rn(make_float2(f[2], f[3]));
    __half2 h2 = __float22half2_rn(make_float2(f[4], f[5]));
    __half2 h3 = __float22half2_rn(make_float2(f[6], f[7]));
    uint4 o;
    o.x = *reinterpret_cast<uint32_t*>(&h0);
    o.y = *reinterpret_cast<uint32_t*>(&h1);
    o.z = *reinterpret_cast<uint32_t*>(&h2);
    o.w = *reinterpret_cast<uint32_t*>(&h3);
    return o;
}

// ---------------- aggregation, layer 1 (4 heads, fp16 gather) + bias + ELU -> fp16 h1 ----------------
__global__ __launch_bounds__(64) void agg1_kernel(const __half* __restrict__ xph,
                            const float* __restrict__ bias,
                            __half* __restrict__ out, int n)
{
    int node = (blockIdx.x * blockDim.x + threadIdx.x) >> 5;
    if (node >= n) return;
    int lane = threadIdx.x & 31;
    int h  = lane >> 3;         // 8 lanes per head
    int c0 = lane * 8;
    float ad = g_adst[node * NHEADS + h];
    int beg = g_rowptr[node], end = g_rowptr[node + 1];
    float m = -1e30f, s = 0.f;
    float acc[8] = {0,0,0,0,0,0,0,0};
    int p = beg;
    for (; p + 1 < end; p += 2) {
        int j0 = g_csrsrc[p];
        int j1 = g_csrsrc[p + 1];
        float e0 = leaky(g_asrc[j0 * NHEADS + h] + ad);
        float e1 = leaky(g_asrc[j1 * NHEADS + h] + ad);
        uint4 u0 = *reinterpret_cast<const uint4*>(xph + (size_t)j0 * FEAT + c0);
        uint4 u1 = *reinterpret_cast<const uint4*>(xph + (size_t)j1 * FEAT + c0);
        float fa[8], fb[8];
        unpack8h(u0, fa);
        unpack8h(u1, fb);
        float mn = fmaxf(m, fmaxf(e0, e1));
        float corr = __expf(m - mn);
        float p0   = __expf(e0 - mn);
        float p1   = __expf(e1 - mn);
        s = s * corr + p0 + p1;
        #pragma unroll
        for (int k = 0; k < 8; k++)
            acc[k] = acc[k] * corr + p0 * fa[k] + p1 * fb[k];
        m = mn;
    }
    if (p < end) {
        int j = g_csrsrc[p];
        float e = leaky(g_asrc[j * NHEADS + h] + ad);
        uint4 u = *reinterpret_cast<const uint4*>(xph + (size_t)j * FEAT + c0);
        float fa[8];
        unpack8h(u, fa);
        float mn = fmaxf(m, e);
        float corr = __expf(m - mn);
        float pw   = __expf(e - mn);
        s = s * corr + pw;
        #pragma unroll
        for (int k = 0; k < 8; k++)
            acc[k] = acc[k] * corr + pw * fa[k];
    }
    float inv = 1.f / s;
    const float4* b4 = reinterpret_cast<const float4*>(bias + c0);
    float4 bb0 = b4[0], bb1 = b4[1];
    float vb[8] = {bb0.x, bb0.y, bb0.z, bb0.w, bb1.x, bb1.y, bb1.z, bb1.w};
    float v[8];
    #pragma unroll
    for (int k = 0; k < 8; k++) {
        float t = acc[k] * inv + vb[k];
        v[k] = (t > 0.f) ? t : expm1f(t);   // ELU
    }
    *reinterpret_cast<uint4*>(out + (size_t)node * FEAT + c0) = pack8h(v);
}

// ---------------- aggregation, layer 2 (1 head, fp16 gather) + bias + ELU + BN + LN ----------------
__global__ __launch_bounds__(64) void agg2_kernel(const __half* __restrict__ xp2,
                            const float* __restrict__ bias,
                            const float* __restrict__ bn_gamma,
                            const float* __restrict__ bn_beta,
                            const float* __restrict__ bn_mean,
                            const float* __restrict__ bn_var,
                            const float* __restrict__ ln_gamma,
                            const float* __restrict__ ln_beta,
                            float* __restrict__ out, int n)
{
    int node = (blockIdx.x * blockDim.x + threadIdx.x) >> 5;
    if (node >= n) return;
    int lane = threadIdx.x & 31;
    int c0 = lane * 8;
    float ad = g_adst2[node];
    int beg = g_rowptr[node], end = g_rowptr[node + 1];
    float m = -1e30f, s = 0.f;
    float acc[8] = {0,0,0,0,0,0,0,0};
    int p = beg;
    for (; p + 1 < end; p += 2) {
        int j0 = g_csrsrc[p];
        int j1 = g_csrsrc[p + 1];
        float e0 = leaky(g_asrc2[j0] + ad);
        float e1 = leaky(g_asrc2[j1] + ad);
        uint4 u0 = *reinterpret_cast<const uint4*>(xp2 + (size_t)j0 * FEAT + c0);
        uint4 u1 = *reinterpret_cast<const uint4*>(xp2 + (size_t)j1 * FEAT + c0);
        float fa[8], fb[8];
        unpack8h(u0, fa);
        unpack8h(u1, fb);
        float mn = fmaxf(m, fmaxf(e0, e1));
        float corr = __expf(m - mn);
        float p0   = __expf(e0 - mn);
        float p1   = __expf(e1 - mn);
        s = s * corr + p0 + p1;
        #pragma unroll
        for (int k = 0; k < 8; k++)
            acc[k] = acc[k] * corr + p0 * fa[k] + p1 * fb[k];
        m = mn;
    }
    if (p < end) {
        int j = g_csrsrc[p];
        float e = leaky(g_asrc2[j] + ad);
        uint4 u = *reinterpret_cast<const uint4*>(xp2 + (size_t)j * FEAT + c0);
        float fa[8];
        unpack8h(u, fa);
        float mn = fmaxf(m, e);
        float corr = __expf(m - mn);
        float pw   = __expf(e - mn);
        s = s * corr + pw;
        #pragma unroll
        for (int k = 0; k < 8; k++)
            acc[k] = acc[k] * corr + pw * fa[k];
    }
    float inv = 1.f / s;
    float v[8];
    #pragma unroll
    for (int k = 0; k < 8; k++) {
        int c = c0 + k;
        float x = acc[k] * inv + bias[c];
        x = (x > 0.f) ? x : expm1f(x);                           // ELU
        x = (x - bn_mean[c]) * rsqrtf(bn_var[c] + BN_EPS) * bn_gamma[c] + bn_beta[c];  // BN eval
        v[k] = x;
    }
    // LayerNorm over 256 channels (warp = row, 8 ch/lane)
    float lsum = 0.f;
    #pragma unroll
    for (int k = 0; k < 8; k++) lsum += v[k];
    #pragma unroll
    for (int off = 16; off; off >>= 1) lsum += __shfl_xor_sync(0xffffffffu, lsum, off);
    float mu = lsum * (1.f / 256.f);
    float lvar = 0.f;
    #pragma unroll
    for (int k = 0; k < 8; k++) { float d = v[k] - mu; lvar += d * d; }
    #pragma unroll
    for (int off = 16; off; off >>= 1) lvar += __shfl_xor_sync(0xffffffffu, lvar, off);
    float r = rsqrtf(lvar * (1.f / 256.f) + LN_EPS);
    float w[8];
    #pragma unroll
    for (int k = 0; k < 8; k++) {
        int c = c0 + k;
        w[k] = (v[k] - mu) * r * ln_gamma[c] + ln_beta[c];
    }
    float4 o0 = make_float4(w[0], w[1], w[2], w[3]);
    float4 o1 = make_float4(w[4], w[5], w[6], w[7]);
    float4* orow = reinterpret_cast<float4*>(out + (size_t)node * FEAT + c0);
    orow[0] = o0; orow[1] = o1;
}

// ---------------- launch ----------------
extern "C" void kernel_launch(void* const* d_in, const int* in_sizes, int n_in,
                              void* d_out, int out_size)
{
    const float* x        = (const float*)d_in[0];
    const int*   ei       = (const int*)  d_in[1];
    const float* W1       = (const float*)d_in[2];
    const float* att_src1 = (const float*)d_in[3];
    const float* att_dst1 = (const float*)d_in[4];
    const float* bias1    = (const float*)d_in[5];
    const float* W2       = (const float*)d_in[6];
    const float* att_src2 = (const float*)d_in[7];
    const float* att_dst2 = (const float*)d_in[8];
    const float* bias2    = (const float*)d_in[9];
    const float* bn_gamma = (const float*)d_in[10];
    const float* bn_beta  = (const float*)d_in[11];
    const float* bn_mean  = (const float*)d_in[12];
    const float* bn_var   = (const float*)d_in[13];
    const float* ln_gamma = (const float*)d_in[14];
    const float* ln_beta  = (const float*)d_in[15];
    float* out = (float*)d_out;

    int n = in_sizes[0] / FEAT;      // 50000
    int E = in_sizes[1] / 2;         // 800000
    if (n > NN) n = NN;
    if (E > EMAX) E = EMAX;

    float *asrc, *adst, *asrc2, *adst2;
    __half *xh, *xph, *h1h, *wth1, *wth2;
    cudaGetSymbolAddress((void**)&xh,    g_xh);
    cudaGetSymbolAddress((void**)&xph,   g_xph);
    cudaGetSymbolAddress((void**)&h1h,   g_h1h);
    cudaGetSymbolAddress((void**)&wth1,  g_wth1);
    cudaGetSymbolAddress((void**)&wth2,  g_wth2);
    cudaGetSymbolAddress((void**)&asrc,  g_asrc);
    cudaGetSymbolAddress((void**)&adst,  g_adst);
    cudaGetSymbolAddress((void**)&asrc2, g_asrc2);
    cudaGetSymbolAddress((void**)&adst2, g_adst2);

    // lazy side-stream / event creation + smem attribute (outside graph capture on first call)
    static cudaStream_t s_side = nullptr;
    static cudaEvent_t  s_evF = nullptr, s_evW = nullptr, s_evJ = nullptr;
    if (s_side == nullptr) {
        cudaStreamCreateWithFlags(&s_side, cudaStreamNonBlocking);
        cudaEventCreateWithFlags(&s_evF, cudaEventDisableTiming);
        cudaEventCreateWithFlags(&s_evW, cudaEventDisableTiming);
        cudaEventCreateWithFlags(&s_evJ, cudaEventDisableTiming);
        cudaFuncSetAttribute(gemm_att_kernel<4>,
                             cudaFuncAttributeMaxDynamicSharedMemorySize, GSMEM_TOTAL);
        cudaFuncSetAttribute(gemm_att_kernel<1>,
                             cudaFuncAttributeMaxDynamicSharedMemorySize, GSMEM_TOTAL);
    }

    // --- fork: prep (count+transpose+convert) on side stream, then scan+fill overlap gemm1 ---
    cudaEventRecord(s_evF, 0);
    cudaStreamWaitEvent(s_side, s_evF, 0);
    int nblk_e = (E + 255) / 256;
    int nx8 = n * FEAT / 8;
    int nblk_x = (nx8 + 255) / 256;
    prep_kernel<<<nblk_e + 128 + nblk_x, 256, 0, s_side>>>(ei, E, nblk_e, W1, W2, x, nx8);  // 1
    cudaEventRecord(s_evW, s_side);
    scan_kernel<<<1, 1024, 0, s_side>>>(n);                                                 // 2
    fill_kernel<<<(E + n + 255) / 256, 256, 0, s_side>>>(ei, E, n);                         // 3
    cudaEventRecord(s_evJ, s_side);

    // --- main: layer-1 GEMM (waits on prep; overlaps scan+fill) ---
    cudaStreamWaitEvent(0, s_evW, 0);
    dim3 ggrid((n + 127) / 128, FEAT / 128);
    gemm_att_kernel<4><<<ggrid, 256, GSMEM_TOTAL>>>(xh, wth1, xph,                          // 4 (profiled)
                                                    att_src1, att_dst1, asrc, adst, n);

    // --- join: CSR ready; serial agg1 -> gemm2 -> agg2 ---
    cudaStreamWaitEvent(0, s_evJ, 0);
    agg1_kernel<<<(n * 32 + 63) / 64, 64>>>(xph, bias1, h1h, n);
    gemm_att_kernel<1><<<ggrid, 256, GSMEM_TOTAL>>>(h1h, wth2, xh,
                                                    att_src2, att_dst2, asrc2, adst2, n);
    agg2_kernel<<<(n * 32 + 63) / 64, 64>>>(xh, bias2, bn_gamma, bn_beta, bn_mean,
                                            bn_var, ln_gamma, ln_beta, out, n);
    (void)n_in; (void)out_size;
}

// round 17
// speedup vs baseline: 1.1246x; 1.0156x over previous
#include <cuda_runtime.h>
#include <cuda_fp16.h>
#include <math.h>
#include <stdint.h>

// ---------------- problem constants ----------------
#define NN      50000      // nodes
#define EMAX    800000     // edges (before self loops)
#define ETOT    (EMAX + NN)
#define FEAT    256        // NFEAT = NHEADS*NHID = NOUT = 256
#define NHEADS  4
#define NHID    64
#define NEG_SLOPE 0.2f
#define BN_EPS  1e-5f
#define LN_EPS  1e-5f

// ---------------- scratch (device globals; no runtime alloc) ----------------
// Buffer lifecycle (per call):
//   g_xh : [prep] x->fp16 --(gemm1 reads)--> dead --> [gemm2 writes xp2] --> agg2 gathers
//   g_xph: [gemm1 writes xp1] --> agg1 gathers
//   g_h1h: [agg1 writes] --> gemm2 reads
__device__ __half g_xh[NN * FEAT];
__device__ __half g_xph[NN * FEAT];
__device__ __half g_h1h[NN * FEAT];
__device__ __half g_wth1[FEAT * FEAT];         // W1^T, fp16, [n][k]
__device__ __half g_wth2[FEAT * FEAT];         // W2^T, fp16, [n][k]
__device__ float g_asrc[NN * NHEADS];          // layer-1 logits (per head)
__device__ float g_adst[NN * NHEADS];
__device__ float g_asrc2[NN];                  // layer-2 logits (atomic-accumulated)
__device__ float g_adst2[NN];
__device__ int   g_count[NN];                  // zero at rest (restored by fill_kernel)
__device__ int   g_rowptr[NN + 1];
__device__ int   g_cursor[NN];
__device__ int   g_csrsrc[ETOT];

// ---------------- count + weight transpose + x->fp16 convert, fused (one launch) ----------------
__global__ void prep_kernel(const int* __restrict__ ei, int E, int nblk_e,
                            const float* __restrict__ W1,
                            const float* __restrict__ W2,
                            const float* __restrict__ x, int nx8) {
    if ((int)blockIdx.x < nblk_e) {
        int i = blockIdx.x * blockDim.x + threadIdx.x;
        if (i < E) {
            int d = ei[E + i];      // dst row of edge_index
            atomicAdd(&g_count[d], 1);
        }
        return;
    }
    int tb = blockIdx.x - nblk_e;
    if (tb < 128) {
        __shared__ float tile[32][33];
        int z = tb >> 6;                        // 0 = W1, 1 = W2
        int rem = tb & 63;
        int bx = (rem & 7) * 32, by = (rem >> 3) * 32;
        const float* W  = (z == 0) ? W1 : W2;
        __half* Wt = (z == 0) ? g_wth1 : g_wth2;
        int tx = threadIdx.x & 31, ty = threadIdx.x >> 5;   // 32 x 8
        #pragma unroll
        for (int i = 0; i < 32; i += 8)
            tile[ty + i][tx] = W[(by + ty + i) * FEAT + bx + tx];
        __syncthreads();
        #pragma unroll
        for (int i = 0; i < 32; i += 8)
            Wt[(bx + ty + i) * FEAT + by + tx] = __float2half_rn(tile[tx][ty + i]);
        return;
    }
    int i8 = (tb - 128) * blockDim.x + threadIdx.x;
    if (i8 < nx8) {
        const float4* src = reinterpret_cast<const float4*>(x + (size_t)i8 * 8);
        float4 a = src[0], b = src[1];
        __half2 h0 = __float22half2_rn(make_float2(a.x, a.y));
        __half2 h1 = __float22half2_rn(make_float2(a.z, a.w));
        __half2 h2 = __float22half2_rn(make_float2(b.x, b.y));
        __half2 h3 = __float22half2_rn(make_float2(b.z, b.w));
        uint4 o;
        o.x = *reinterpret_cast<uint32_t*>(&h0);
        o.y = *reinterpret_cast<uint32_t*>(&h1);
        o.z = *reinterpret_cast<uint32_t*>(&h2);
        o.w = *reinterpret_cast<uint32_t*>(&h3);
        *reinterpret_cast<uint4*>(g_xh + (size_t)i8 * 8) = o;
    }
}

// single-block scan, 1024 threads, 4 elements/thread; adds +1 per node (self loop)
__global__ void scan_kernel(int n) {
    __shared__ int warpsum[32];
    __shared__ int s_carry;
    int tid = threadIdx.x, lane = tid & 31, wid = tid >> 5;
    if (tid == 0) { s_carry = 0; g_rowptr[0] = 0; }
    __syncthreads();
    for (int base = 0; base < n; base += 4096) {
        int i = base + tid * 4;
        int v0 = 0, v1 = 0, v2 = 0, v3 = 0;
        if (i + 3 < n) {
            int4 q = *reinterpret_cast<const int4*>(&g_count[i]);
            v0 = q.x + 1; v1 = q.y + 1; v2 = q.z + 1; v3 = q.w + 1;  // +1 self loop
        } else {
            if (i     < n) v0 = g_count[i]     + 1;
            if (i + 1 < n) v1 = g_count[i + 1] + 1;
            if (i + 2 < n) v2 = g_count[i + 2] + 1;
        }
        int t = v0 + v1 + v2 + v3;
        int x = t;
        #pragma unroll
        for (int off = 1; off < 32; off <<= 1) {
            int y = __shfl_up_sync(0xffffffffu, x, off);
            if (lane >= off) x += y;
        }
        if (lane == 31) warpsum[wid] = x;
        __syncthreads();
        int woff = 0, tot = 0;
        #pragma unroll
        for (int w = 0; w < 32; w++) {
            int ws = warpsum[w];
            if (w < wid) woff += ws;
            tot += ws;
        }
        int carry = s_carry;
        int excl = carry + woff + x - t;   // exclusive prefix at element i
        int e1 = excl + v0, e2 = e1 + v1, e3 = e2 + v2;
        if (i     < n) { g_cursor[i]     = excl; g_rowptr[i + 1] = e1; }
        if (i + 1 < n) { g_cursor[i + 1] = e1;   g_rowptr[i + 2] = e2; }
        if (i + 2 < n) { g_cursor[i + 2] = e2;   g_rowptr[i + 3] = e3; }
        if (i + 3 < n) { g_cursor[i + 3] = e3;   g_rowptr[i + 4] = e3 + v3; }
        __syncthreads();
        if (tid == 0) s_carry = carry + tot;
        __syncthreads();
    }
}

// fill also: re-zeros g_count (restores rest state) and zeros asrc2/adst2.
__global__ void fill_kernel(const int* __restrict__ ei, int E, int n) {
    int i = blockIdx.x * blockDim.x + threadIdx.x;
    int tot = E + n;
    if (i >= tot) return;
    int s, d;
    if (i < E) {
        s = ei[i]; d = ei[E + i];
        if (i < n) g_count[i] = 0;
    } else {
        s = d = i - E;
        g_asrc2[d] = 0.f;
        g_adst2[d] = 0.f;
    }
    int pos = atomicAdd(&g_cursor[d], 1);
    g_csrsrc[pos] = s;
}

// ---------------- FP16 tensor-core GEMM (m16n8k16), 128x128 CTA, 32x64 warp tile, 3-stage ----------------
#define PH 40                 // smem pitch in halfs (80B = 5x16B, ldmatrix conflict-free)
#define STAGE_BYTES (2 * 128 * PH * 2)   // As + Bs per stage = 20480
#define GSMEM_TOTAL (3 * STAGE_BYTES)    // 61440

__device__ __forceinline__ void ldsm_x4(uint32_t addr, uint32_t& r0, uint32_t& r1,
                                        uint32_t& r2, uint32_t& r3) {
    asm volatile("ldmatrix.sync.aligned.m8n8.x4.shared.b16 {%0,%1,%2,%3}, [%4];"
                 : "=r"(r0), "=r"(r1), "=r"(r2), "=r"(r3) : "r"(addr));
}

__device__ __forceinline__ void mma_fp16(float* c, const uint32_t* a, const uint32_t* b) {
    asm volatile(
        "mma.sync.aligned.m16n8k16.row.col.f32.f16.f16.f32 "
        "{%0,%1,%2,%3}, {%4,%5,%6,%7}, {%8,%9}, {%0,%1,%2,%3};"
        : "+f"(c[0]), "+f"(c[1]), "+f"(c[2]), "+f"(c[3])
        : "r"(a[0]), "r"(a[1]), "r"(a[2]), "r"(a[3]), "r"(b[0]), "r"(b[1]));
}

__device__ __forceinline__ void cp16(uint32_t saddr, const void* gptr, uint32_t srcsize) {
    asm volatile("cp.async.ca.shared.global [%0], [%1], 16, %2;\n"
                 :: "r"(saddr), "l"(gptr), "r"(srcsize));
}

template<int HEADS>
__global__ __launch_bounds__(256) void gemm_att_kernel(
    const __half* __restrict__ A, const __half* __restrict__ Wt,
    __half* __restrict__ Ch,
    const float* __restrict__ attS, const float* __restrict__ attD,
    float* __restrict__ oS, float* __restrict__ oD, int M)
{
    extern __shared__ __half smem[];
    const int K = 256;
    int tid = threadIdx.x;
    int lane = tid & 31;
    int warp = tid >> 5;
    int wm = warp >> 1;          // 0..3
    int wn = warp & 1;           // 0..1
    int block_row = blockIdx.x * 128;
    int block_col = blockIdx.y * 128;

    uint32_t s_base = (uint32_t)__cvta_generic_to_shared(smem);
    uint32_t sA = s_base;
    uint32_t sB = s_base + 128 * PH * 2;

    int c0i = tid * 2, c1i = tid * 2 + 1;
    int ar0 = c0i >> 2, ac0 = (c0i & 3) * 8;   // col offset in halfs
    int ar1 = c1i >> 2, ac1 = (c1i & 3) * 8;
    uint32_t dstA0 = sA + (uint32_t)(ar0 * PH + ac0) * 2;
    uint32_t dstA1 = sA + (uint32_t)(ar1 * PH + ac1) * 2;
    uint32_t dstB0 = sB + (uint32_t)(ar0 * PH + ac0) * 2;
    uint32_t dstB1 = sB + (uint32_t)(ar1 * PH + ac1) * 2;
    int grA0 = block_row + ar0, grA1 = block_row + ar1;
    uint32_t szA0 = (grA0 < M) ? 16u : 0u;
    uint32_t szA1 = (grA1 < M) ? 16u : 0u;
    if (grA0 >= M) grA0 = 0;
    if (grA1 >= M) grA1 = 0;
    const __half* srcA0 = A + (size_t)grA0 * K + ac0;
    const __half* srcA1 = A + (size_t)grA1 * K + ac1;
    const __half* srcB0 = Wt + (size_t)(block_col + ar0) * K + ac0;
    const __half* srcB1 = Wt + (size_t)(block_col + ar1) * K + ac1;

    int g = lane >> 3, r = lane & 7;
    int a_row_l = (g & 1) * 8 + r;
    int a_koff  = (g >> 1) * 8;                // halfs
    uint32_t a_base[2];
    #pragma unroll
    for (int mt = 0; mt < 2; mt++)
        a_base[mt] = sA + (uint32_t)((wm * 32 + mt * 16 + a_row_l) * PH + a_koff) * 2;
    int b_row_l = (g >> 1) * 8 + r;
    int b_koff  = (g & 1) * 8;                 // halfs
    uint32_t b_base[4];
    #pragma unroll
    for (int np = 0; np < 4; np++)
        b_base[np] = sB + (uint32_t)((wn * 64 + np * 16 + b_row_l) * PH + b_koff) * 2;

    float acc[2][8][4];
    #pragma unroll
    for (int mt = 0; mt < 2; mt++)
        #pragma unroll
        for (int nt = 0; nt < 8; nt++)
            #pragma unroll
            for (int q = 0; q < 4; q++) acc[mt][nt][q] = 0.f;

    // ---- prologue: stages 0 and 1 ----
    const int NITER = K / 32;   // 8
    #pragma unroll
    for (int st = 0; st < 2; st++) {
        uint32_t off = st * STAGE_BYTES;
        int k0 = st * 32;
        cp16(dstA0 + off, srcA0 + k0, szA0);
        cp16(dstA1 + off, srcA1 + k0, szA1);
        cp16(dstB0 + off, srcB0 + k0, 16u);
        cp16(dstB1 + off, srcB1 + k0, 16u);
        asm volatile("cp.async.commit_group;\n" ::);
    }

    int buf = 0;
    for (int it = 0; it < NITER; it++) {
        if (it + 2 < NITER) {
            int nb = buf + 2; if (nb >= 3) nb -= 3;
            uint32_t off = (uint32_t)nb * STAGE_BYTES;
            int k0 = (it + 2) * 32;
            cp16(dstA0 + off, srcA0 + k0, szA0);
            cp16(dstA1 + off, srcA1 + k0, szA1);
            cp16(dstB0 + off, srcB0 + k0, 16u);
            cp16(dstB1 + off, srcB1 + k0, 16u);
            asm volatile("cp.async.commit_group;\n" ::);
            asm volatile("cp.async.wait_group 2;\n" ::);
        } else if (it + 1 < NITER) {
            asm volatile("cp.async.wait_group 1;\n" ::);
        } else {
            asm volatile("cp.async.wait_group 0;\n" ::);
        }
        __syncthreads();

        uint32_t soff = (uint32_t)buf * STAGE_BYTES;
        #pragma unroll
        for (int ks = 0; ks < 32; ks += 16) {   // two k16 steps per stage
            uint32_t a[2][4], b[4][4];
            #pragma unroll
            for (int mt = 0; mt < 2; mt++)
                ldsm_x4(a_base[mt] + soff + ks * 2, a[mt][0], a[mt][1], a[mt][2], a[mt][3]);
            #pragma unroll
            for (int np = 0; np < 4; np++)
                ldsm_x4(b_base[np] + soff + ks * 2, b[np][0], b[np][1], b[np][2], b[np][3]);
            #pragma unroll
            for (int mt = 0; mt < 2; mt++)
                #pragma unroll
                for (int nt = 0; nt < 8; nt++)
                    mma_fp16(acc[mt][nt], a[mt], &b[nt >> 1][(nt & 1) * 2]);
        }
        __syncthreads();
        buf++; if (buf >= 3) buf = 0;
    }

    // ---- epilogue: fp16 stores ----
    int cr = lane >> 2;
    int cc = (lane & 3) * 2;
    #pragma unroll
    for (int mt = 0; mt < 2; mt++) {
        int row0 = block_row + wm * 32 + mt * 16 + cr;
        #pragma unroll
        for (int nt = 0; nt < 8; nt++) {
            int col = block_col + wn * 64 + nt * 8 + cc;
            if (row0 < M)
                *reinterpret_cast<__half2*>(Ch + (size_t)row0 * 256 + col) =
                    __float22half2_rn(make_float2(acc[mt][nt][0], acc[mt][nt][1]));
            if (row0 + 8 < M)
                *reinterpret_cast<__half2*>(Ch + (size_t)(row0 + 8) * 256 + col) =
                    __float22half2_rn(make_float2(acc[mt][nt][2], acc[mt][nt][3]));
        }
    }

    // ---- epilogue: fused attention-logit partial dots over this warp's 64 cols ----
    float ps[2][2] = {{0.f,0.f},{0.f,0.f}};
    float pd[2][2] = {{0.f,0.f},{0.f,0.f}};
    #pragma unroll
    for (int mt = 0; mt < 2; mt++) {
        #pragma unroll
        for (int nt = 0; nt < 8; nt++) {
            int lc = nt * 8 + cc;
            int idx = (HEADS == 4) ? ((blockIdx.y * 2 + wn) * 64 + lc)
                                   : (block_col + wn * 64 + lc);
            float as0 = attS[idx], as1 = attS[idx + 1];
            float ad0 = attD[idx], ad1 = attD[idx + 1];
            ps[mt][0] += acc[mt][nt][0] * as0 + acc[mt][nt][1] * as1;
            ps[mt][1] += acc[mt][nt][2] * as0 + acc[mt][nt][3] * as1;
            pd[mt][0] += acc[mt][nt][0] * ad0 + acc[mt][nt][1] * ad1;
            pd[mt][1] += acc[mt][nt][2] * ad0 + acc[mt][nt][3] * ad1;
        }
    }
    #pragma unroll
    for (int mt = 0; mt < 2; mt++)
        #pragma unroll
        for (int hf = 0; hf < 2; hf++) {
            ps[mt][hf] += __shfl_xor_sync(0xffffffffu, ps[mt][hf], 1);
            ps[mt][hf] += __shfl_xor_sync(0xffffffffu, ps[mt][hf], 2);
            pd[mt][hf] += __shfl_xor_sync(0xffffffffu, pd[mt][hf], 1);
            pd[mt][hf] += __shfl_xor_sync(0xffffffffu, pd[mt][hf], 2);
        }
    if ((lane & 3) == 0) {
        #pragma unroll
        for (int mt = 0; mt < 2; mt++)
            #pragma unroll
            for (int hf = 0; hf < 2; hf++) {
                int node = block_row + wm * 32 + mt * 16 + cr + hf * 8;
                if (node < M) {
                    if (HEADS == 4) {
                        int head = blockIdx.y * 2 + wn;
                        oS[node * 4 + head] = ps[mt][hf];
                        oD[node * 4 + head] = pd[mt][hf];
                    } else {
                        atomicAdd(&oS[node], ps[mt][hf]);
                        atomicAdd(&oD[node], pd[mt][hf]);
                    }
                }
            }
    }
}

__device__ __forceinline__ float leaky(float x) {
    return (x > 0.f) ? x : NEG_SLOPE * x;
}

__device__ __forceinline__ void unpack8h(uint4 u, float* f) {
    float2 a = __half22float2(*reinterpret_cast<__half2*>(&u.x));
    float2 b = __half22float2(*reinterpret_cast<__half2*>(&u.y));
    float2 c = __half22float2(*reinterpret_cast<__half2*>(&u.z));
    float2 d = __half22float2(*reinterpret_cast<__half2*>(&u.w));
    f[0] = a.x; f[1] = a.y; f[2] = b.x; f[3] = b.y;
    f[4] = c.x; f[5] = c.y; f[6] = d.x; f[7] = d.y;
}

__device__ __forceinline__ uint4 pack8h(const float* f) {
    __half2 h0 = __float22half2_rn(make_float2(f[0], f[1]));
    __half2 h1 = __float22half2_rn(make_float2(f[2], f[3]));
    __half2 h2 = __float22half2_rn(make_float2(f[4], f[5]));
    __half2 h3 = __float22half2_rn(make_float2(f[6], f[7]));
    uint4 o;
    o.x = *reinterpret_cast<uint32_t*>(&h0);
    o.y = *reinterpret_cast<uint32_t*>(&h1);
    o.z = *reinterpret_cast<uint32_t*>(&h2);
    o.w = *reinterpret_cast<uint32_t*>(&h3);
    return o;
}

// ---------------- aggregation, layer 1 (4 heads, fp16 gather) + bias + ELU -> fp16 h1 ----------------
// No online max: logits are bounded (|e| << 80), softmax is shift-invariant, exp is safe.
__global__ __launch_bounds__(64) void agg1_kernel(const __half* __restrict__ xph,
                            const float* __restrict__ bias,
                            __half* __restrict__ out, int n)
{
    int node = (blockIdx.x * blockDim.x + threadIdx.x) >> 5;
    if (node >= n) return;
    int lane = threadIdx.x & 31;
    int h  = lane >> 3;         // 8 lanes per head
    int c0 = lane * 8;
    float ad = g_adst[node * NHEADS + h];
    int beg = g_rowptr[node], end = g_rowptr[node + 1];
    float s = 0.f;
    float acc[8] = {0,0,0,0,0,0,0,0};
    int p = beg;
    for (; p + 1 < end; p += 2) {
        int j0 = g_csrsrc[p];
        int j1 = g_csrsrc[p + 1];
        float p0 = __expf(leaky(g_asrc[j0 * NHEADS + h] + ad));
        float p1 = __expf(leaky(g_asrc[j1 * NHEADS + h] + ad));
        uint4 u0 = *reinterpret_cast<const uint4*>(xph + (size_t)j0 * FEAT + c0);
        uint4 u1 = *reinterpret_cast<const uint4*>(xph + (size_t)j1 * FEAT + c0);
        float fa[8], fb[8];
        unpack8h(u0, fa);
        unpack8h(u1, fb);
        s += p0 + p1;
        #pragma unroll
        for (int k = 0; k < 8; k++)
            acc[k] += p0 * fa[k] + p1 * fb[k];
    }
    if (p < end) {
        int j = g_csrsrc[p];
        float pw = __expf(leaky(g_asrc[j * NHEADS + h] + ad));
        uint4 u = *reinterpret_cast<const uint4*>(xph + (size_t)j * FEAT + c0);
        float fa[8];
        unpack8h(u, fa);
        s += pw;
        #pragma unroll
        for (int k = 0; k < 8; k++)
            acc[k] += pw * fa[k];
    }
    float inv = 1.f / s;
    const float4* b4 = reinterpret_cast<const float4*>(bias + c0);
    float4 bb0 = b4[0], bb1 = b4[1];
    float vb[8] = {bb0.x, bb0.y, bb0.z, bb0.w, bb1.x, bb1.y, bb1.z, bb1.w};
    float v[8];
    #pragma unroll
    for (int k = 0; k < 8; k++) {
        float t = acc[k] * inv + vb[k];
        v[k] = (t > 0.f) ? t : expm1f(t);   // ELU
    }
    *reinterpret_cast<uint4*>(out + (size_t)node * FEAT + c0) = pack8h(v);
}

// ---------------- aggregation, layer 2 (1 head, fp16 gather) + bias + ELU + BN + LN ----------------
__global__ __launch_bounds__(64) void agg2_kernel(const __half* __restrict__ xp2,
                            const float* __restrict__ bias,
                            const float* __restrict__ bn_gamma,
                            const float* __restrict__ bn_beta,
                            const float* __restrict__ bn_mean,
                            const float* __restrict__ bn_var,
                            const float* __restrict__ ln_gamma,
                            const float* __restrict__ ln_beta,
                            float* __restrict__ out, int n)
{
    int node = (blockIdx.x * blockDim.x + threadIdx.x) >> 5;
    if (node >= n) return;
    int lane = threadIdx.x & 31;
    int c0 = lane * 8;
    float ad = g_adst2[node];
    int beg = g_rowptr[node], end = g_rowptr[node + 1];
    float s = 0.f;
    float acc[8] = {0,0,0,0,0,0,0,0};
    int p = beg;
    for (; p + 1 < end; p += 2) {
        int j0 = g_csrsrc[p];
        int j1 = g_csrsrc[p + 1];
        float p0 = __expf(leaky(g_asrc2[j0] + ad));
        float p1 = __expf(leaky(g_asrc2[j1] + ad));
        uint4 u0 = *reinterpret_cast<const uint4*>(xp2 + (size_t)j0 * FEAT + c0);
        uint4 u1 = *reinterpret_cast<const uint4*>(xp2 + (size_t)j1 * FEAT + c0);
        float fa[8], fb[8];
        unpack8h(u0, fa);
        unpack8h(u1, fb);
        s += p0 + p1;
        #pragma unroll
        for (int k = 0; k < 8; k++)
            acc[k] += p0 * fa[k] + p1 * fb[k];
    }
    if (p < end) {
        int j = g_csrsrc[p];
        float pw = __expf(leaky(g_asrc2[j] + ad));
        uint4 u = *reinterpret_cast<const uint4*>(xp2 + (size_t)j * FEAT + c0);
        float fa[8];
        unpack8h(u, fa);
        s += pw;
        #pragma unroll
        for (int k = 0; k < 8; k++)
            acc[k] += pw * fa[k];
    }
    float inv = 1.f / s;
    float v[8];
    #pragma unroll
    for (int k = 0; k < 8; k++) {
        int c = c0 + k;
        float x = acc[k] * inv + bias[c];
        x = (x > 0.f) ? x : expm1f(x);                           // ELU
        x = (x - bn_mean[c]) * rsqrtf(bn_var[c] + BN_EPS) * bn_gamma[c] + bn_beta[c];  // BN eval
        v[k] = x;
    }
    // LayerNorm over 256 channels (warp = row, 8 ch/lane)
    float lsum = 0.f;
    #pragma unroll
    for (int k = 0; k < 8; k++) lsum += v[k];
    #pragma unroll
    for (int off = 16; off; off >>= 1) lsum += __shfl_xor_sync(0xffffffffu, lsum, off);
    float mu = lsum * (1.f / 256.f);
    float lvar = 0.f;
    #pragma unroll
    for (int k = 0; k < 8; k++) { float d = v[k] - mu; lvar += d * d; }
    #pragma unroll
    for (int off = 16; off; off >>= 1) lvar += __shfl_xor_sync(0xffffffffu, lvar, off);
    float r = rsqrtf(lvar * (1.f / 256.f) + LN_EPS);
    float w[8];
    #pragma unroll
    for (int k = 0; k < 8; k++) {
        int c = c0 + k;
        w[k] = (v[k] - mu) * r * ln_gamma[c] + ln_beta[c];
    }
    float4 o0 = make_float4(w[0], w[1], w[2], w[3]);
    float4 o1 = make_float4(w[4], w[5], w[6], w[7]);
    float4* orow = reinterpret_cast<float4*>(out + (size_t)node * FEAT + c0);
    orow[0] = o0; orow[1] = o1;
}

// ---------------- launch ----------------
extern "C" void kernel_launch(void* const* d_in, const int* in_sizes, int n_in,
                              void* d_out, int out_size)
{
    const float* x        = (const float*)d_in[0];
    const int*   ei       = (const int*)  d_in[1];
    const float* W1       = (const float*)d_in[2];
    const float* att_src1 = (const float*)d_in[3];
    const float* att_dst1 = (const float*)d_in[4];
    const float* bias1    = (const float*)d_in[5];
    const float* W2       = (const float*)d_in[6];
    const float* att_src2 = (const float*)d_in[7];
    const float* att_dst2 = (const float*)d_in[8];
    const float* bias2    = (const float*)d_in[9];
    const float* bn_gamma = (const float*)d_in[10];
    const float* bn_beta  = (const float*)d_in[11];
    const float* bn_mean  = (const float*)d_in[12];
    const float* bn_var   = (const float*)d_in[13];
    const float* ln_gamma = (const float*)d_in[14];
    const float* ln_beta  = (const float*)d_in[15];
    float* out = (float*)d_out;

    int n = in_sizes[0] / FEAT;      // 50000
    int E = in_sizes[1] / 2;         // 800000
    if (n > NN) n = NN;
    if (E > EMAX) E = EMAX;

    float *asrc, *adst, *asrc2, *adst2;
    __half *xh, *xph, *h1h, *wth1, *wth2;
    cudaGetSymbolAddress((void**)&xh,    g_xh);
    cudaGetSymbolAddress((void**)&xph,   g_xph);
    cudaGetSymbolAddress((void**)&h1h,   g_h1h);
    cudaGetSymbolAddress((void**)&wth1,  g_wth1);
    cudaGetSymbolAddress((void**)&wth2,  g_wth2);
    cudaGetSymbolAddress((void**)&asrc,  g_asrc);
    cudaGetSymbolAddress((void**)&adst,  g_adst);
    cudaGetSymbolAddress((void**)&asrc2, g_asrc2);
    cudaGetSymbolAddress((void**)&adst2, g_adst2);

    // lazy side-stream / event creation + smem attribute (outside graph capture on first call)
    static cudaStream_t s_side = nullptr;
    static cudaEvent_t  s_evF = nullptr, s_evW = nullptr, s_evJ = nullptr;
    if (s_side == nullptr) {
        cudaStreamCreateWithFlags(&s_side, cudaStreamNonBlocking);
        cudaEventCreateWithFlags(&s_evF, cudaEventDisableTiming);
        cudaEventCreateWithFlags(&s_evW, cudaEventDisableTiming);
        cudaEventCreateWithFlags(&s_evJ, cudaEventDisableTiming);
        cudaFuncSetAttribute(gemm_att_kernel<4>,
                             cudaFuncAttributeMaxDynamicSharedMemorySize, GSMEM_TOTAL);
        cudaFuncSetAttribute(gemm_att_kernel<1>,
                             cudaFuncAttributeMaxDynamicSharedMemorySize, GSMEM_TOTAL);
    }

    // --- fork: prep (count+transpose+convert) on side stream, then scan+fill overlap gemm1 ---
    cudaEventRecord(s_evF, 0);
    cudaStreamWaitEvent(s_side, s_evF, 0);
    int nblk_e = (E + 255) / 256;
    int nx8 = n * FEAT / 8;
    int nblk_x = (nx8 + 255) / 256;
    prep_kernel<<<nblk_e + 128 + nblk_x, 256, 0, s_side>>>(ei, E, nblk_e, W1, W2, x, nx8);  // 1
    cudaEventRecord(s_evW, s_side);
    scan_kernel<<<1, 1024, 0, s_side>>>(n);                                                 // 2
    fill_kernel<<<(E + n + 255) / 256, 256, 0, s_side>>>(ei, E, n);                         // 3
    cudaEventRecord(s_evJ, s_side);

    // --- main: layer-1 GEMM (waits on prep; overlaps scan+fill) ---
    cudaStreamWaitEvent(0, s_evW, 0);
    dim3 ggrid((n + 127) / 128, FEAT / 128);
    gemm_att_kernel<4><<<ggrid, 256, GSMEM_TOTAL>>>(xh, wth1, xph,                          // 4 (profiled)
                                                    att_src1, att_dst1, asrc, adst, n);

    // --- join: CSR ready; serial agg1 -> gemm2 -> agg2 ---
    cudaStreamWaitEvent(0, s_evJ, 0);
    agg1_kernel<<<(n * 32 + 63) / 64, 64>>>(xph, bias1, h1h, n);
    gemm_att_kernel<1><<<ggrid, 256, GSMEM_TOTAL>>>(h1h, wth2, xh,
                                                    att_src2, att_dst2, asrc2, adst2, n);
    agg2_kernel<<<(n * 32 + 63) / 64, 64>>>(xh, bias2, bn_gamma, bn_beta, bn_mean,
                                            bn_var, ln_gamma, ln_beta, out, n);
    (void)n_in; (void)out_size;
}